// round 12
// baseline (speedup 1.0000x reference)
#include <cuda_runtime.h>
#include <math.h>

#define NH      8
#define LSEQ    512
#define DRES    384
#define DPAIR   128
#define DS      16
#define TJ      64
#define ROWF    132
#define NROW    1024
#define NFEAT   1280
#define NSPLIT  4
#define KSPLIT  (NFEAT/NSPLIT)

#define SCALE_SCALAR 0.25f
#define SCALE_POINT  0.2357022603955158f   /* 18^-0.5 */
#define SCALE_TOTAL  0.5773502691896258f   /* 3^-0.5  */

typedef unsigned long long ull;

__device__ __forceinline__ ull pk2(float x, float y) {
    ull r; asm("mov.b64 %0,{%1,%2};" : "=l"(r) : "f"(x), "f"(y)); return r;
}
__device__ __forceinline__ ull ffma2(ull a, ull b, ull c) {
    ull d; asm("fma.rn.f32x2 %0,%1,%2,%3;" : "=l"(d) : "l"(a), "l"(b), "l"(c)); return d;
}
__device__ __forceinline__ float2 up2(ull v) {
    float2 r; asm("mov.b64 {%0,%1},%2;" : "=f"(r.x), "=f"(r.y) : "l"(v)); return r;
}
__device__ __forceinline__ void cp_async16(unsigned smem_addr, const void* gptr) {
    asm volatile("cp.async.cg.shared.global [%0], [%1], 16;"
                 :: "r"(smem_addr), "l"(gptr));
}

// ---------------- scratch (device globals; no allocation) ----------------
__device__ float g_qs[2*NH*LSEQ*DS];
__device__ float g_ks[2*NH*LSEQ*DS];
__device__ float g_vs[2*NH*LSEQ*DS];
__device__ float g_qp[2*NH*LSEQ*12];
__device__ float g_kp[2*NH*LSEQ*12];
__device__ float g_vp[2*NH*LSEQ*12];
__device__ float g_praw[NROW*288];
__device__ float g_feat[(size_t)NROW*NFEAT];
__device__ float g_opart[(size_t)NSPLIT*NROW*DRES];
__device__ float g_probs[(size_t)NROW*NH*LSEQ];    // normalized attention

// ---------------- kernel 1: projection GEMM ------------------------------
__global__ void __launch_bounds__(64) proj_gemm(
    const float* __restrict__ X,
    const float* __restrict__ Wqs, const float* __restrict__ Wks,
    const float* __restrict__ Wvs, const float* __restrict__ Wqp,
    const float* __restrict__ Wkp, const float* __restrict__ Wvp)
{
    __shared__ float As[2][16*36];
    __shared__ float Bs[2][16*32];
    const int tid = threadIdx.x;
    const int tx = tid & 7, ty = tid >> 3;
    const int row0 = blockIdx.y * 32;
    const int col0 = blockIdx.x * 32;

    const float* Wseg; int segw, cl0;
    if (col0 < 384) {
        int sg = col0 >> 7;
        Wseg = (sg==0) ? Wqs : ((sg==1) ? Wks : Wvs);
        segw = 128; cl0 = col0 & 127;
    } else {
        int c2 = col0 - 384; int sg = c2 / 96;
        Wseg = (sg==0) ? Wqp : ((sg==1) ? Wkp : Wvp);
        segw = 96; cl0 = c2 - sg*96;
    }

    const int a_m0 = tid >> 2, a_k4 = tid & 3;
    const int b_k0 = tid >> 3, b_n4 = tid & 7;

    float acc[4][4];
    #pragma unroll
    for (int i=0;i<4;i++)
        #pragma unroll
        for (int j=0;j<4;j++) acc[i][j]=0.f;

    {
        #pragma unroll
        for (int s=0;s<2;s++) {
            int m = a_m0 + s*16;
            float4 v = *(const float4*)&X[(size_t)(row0+m)*DRES + a_k4*4];
            #pragma unroll
            for (int u=0;u<4;u++) As[0][(a_k4*4+u)*36 + m] = ((const float*)&v)[u];
            int k = b_k0 + s*8;
            *(float4*)&Bs[0][k*32 + b_n4*4] =
                *(const float4*)&Wseg[(size_t)k*segw + cl0 + b_n4*4];
        }
    }
    __syncthreads();

    const int KB = DRES/16;
    for (int kb = 0; kb < KB; kb++) {
        int cur = kb & 1;
        float4 va[2], vb[2];
        bool has = (kb+1 < KB);
        if (has) {
            int k0 = (kb+1)*16;
            #pragma unroll
            for (int s=0;s<2;s++) {
                int m = a_m0 + s*16;
                va[s] = *(const float4*)&X[(size_t)(row0+m)*DRES + k0 + a_k4*4];
                int k = b_k0 + s*8;
                vb[s] = *(const float4*)&Wseg[(size_t)(k0+k)*segw + cl0 + b_n4*4];
            }
        }
        #pragma unroll
        for (int kk = 0; kk < 16; kk++) {
            float4 a = *(const float4*)&As[cur][kk*36 + ty*4];
            float4 b = *(const float4*)&Bs[cur][kk*32 + tx*4];
            const float* ap = (const float*)&a;
            const float* bp = (const float*)&b;
            #pragma unroll
            for (int i=0;i<4;i++)
                #pragma unroll
                for (int j=0;j<4;j++) acc[i][j] += ap[i]*bp[j];
        }
        if (has) {
            int nxt = cur ^ 1;
            #pragma unroll
            for (int s=0;s<2;s++) {
                int m = a_m0 + s*16;
                #pragma unroll
                for (int u=0;u<4;u++) As[nxt][(a_k4*4+u)*36 + m] = ((const float*)&va[s])[u];
                int k = b_k0 + s*8;
                *(float4*)&Bs[nxt][k*32 + b_n4*4] = vb[s];
            }
        }
        __syncthreads();
    }

    #pragma unroll
    for (int i=0;i<4;i++) {
        int row = row0 + ty*4 + i;
        int b = row >> 9, l = row & 511;
        #pragma unroll
        for (int j=0;j<4;j++) {
            int col = col0 + tx*4 + j;
            float v = acc[i][j];
            if (col < 384) {
                int sg = col >> 7;
                int n = (col & 127) >> 4, d = col & 15;
                float* dst = (sg==0) ? g_qs : ((sg==1) ? g_ks : g_vs);
                dst[(((b*NH)+n)*LSEQ + l)*DS + d] = v;
            } else {
                g_praw[row*288 + (col-384)] = v;
            }
        }
    }
}

// ---------------- kernel 2: euclid transform of projected points ---------
__global__ void point_transform(const float* __restrict__ R, const float* __restrict__ T)
{
    int row = blockIdx.x;
    int b = row >> 9, l = row & 511;
    int t = threadIdx.x;
    if (t >= 96) return;
    int tensor = t / 32, idx = t % 32;
    int n = idx >> 2, p = idx & 3;
    const float* xr = &g_praw[row*288 + tensor*96 + n*12 + p*3];
    const float* rr = &R[row*9];
    const float* tt = &T[row*3];
    float x0 = xr[0], x1 = xr[1], x2 = xr[2];
    float* dst = ((tensor==0) ? g_qp : ((tensor==1) ? g_kp : g_vp))
               + (((b*NH)+n)*LSEQ + l)*12 + p*3;
    #pragma unroll
    for (int c = 0; c < 3; c++)
        dst[c] = x0*rr[0*3+c] + x1*rr[1*3+c] + x2*rr[2*3+c] + tt[c];
}

// ------ kernel 3a: logits + softmax + out_s/out_p + probs to global ------
#define K1_E0     0
#define K1_E1     8448
#define K1_WPB    16896
#define K1_LOGIT  17920          /* [n][512] = 4096 */
#define K1_PART   22016          /* 256*9 = 2304 */
#define K1_QS     24320
#define K1_QP     24448
#define K1_GAMMA  24544
#define K1_OP     24552          /* 96 */
#define K1_FLOATS 24648

__global__ void __launch_bounds__(256) ipa_logits(
    const float* __restrict__ E, const float* __restrict__ R,
    const float* __restrict__ T, const float* __restrict__ Wpb,
    const float* __restrict__ gamma)
{
    extern __shared__ float sm[];
    float* Wpb_s   = sm + K1_WPB;
    float* logit_s = sm + K1_LOGIT;
    float* part_s  = sm + K1_PART;
    float* qs_s    = sm + K1_QS;
    float* qp_s    = sm + K1_QP;
    float* gamma_s = sm + K1_GAMMA;
    float* op_s    = sm + K1_OP;

    int row = blockIdx.x;
    int b = row >> 9, i = row & 511;
    int tid = threadIdx.x;
    int warp = tid >> 5, lane = tid & 31;

    unsigned sbase = (unsigned)__cvta_generic_to_shared(sm);
    const float* Ebi = E + (size_t)row * LSEQ * DPAIR;

    // prologue: tile 0 -> buffer 0
    {
        const float4* esrc = (const float4*)Ebi;
        #pragma unroll
        for (int it = 0; it < 8; it++) {
            int g = it*256 + tid;
            int j = g >> 5, d = (g & 31) * 4;
            cp_async16(sbase + (unsigned)((K1_E0 + j*ROWF + d) * 4), esrc + g);
        }
        asm volatile("cp.async.commit_group;");
    }

    for (int k = tid; k < DPAIR*NH; k += 256) Wpb_s[k] = Wpb[k];
    if (tid < 128) { int n = tid >> 4, d = tid & 15;
        qs_s[tid] = g_qs[((b*NH+n)*LSEQ + i)*DS + d]; }
    if (tid < 96)  { int n = tid/12, pc = tid - n*12;
        qp_s[tid] = g_qp[((b*NH+n)*LSEQ + i)*12 + pc]; }
    if (tid < 8) gamma_s[tid] = gamma[tid];

    for (int jt = 0; jt < LSEQ/TJ; jt++) {
        float* e_s = sm + ((jt & 1) ? K1_E1 : K1_E0);

        if (jt + 1 < LSEQ/TJ) {
            const float4* nsrc = (const float4*)(Ebi + (size_t)(jt+1)*TJ*DPAIR);
            unsigned bofs = (jt & 1) ? K1_E0 : K1_E1;
            #pragma unroll
            for (int it = 0; it < 8; it++) {
                int g = it*256 + tid;
                int j = g >> 5, d = (g & 31) * 4;
                cp_async16(sbase + (unsigned)((bofs + j*ROWF + d) * 4), nsrc + g);
            }
            asm volatile("cp.async.commit_group;");
            asm volatile("cp.async.wait_group 1;");
        } else {
            asm volatile("cp.async.wait_group 0;");
        }
        __syncthreads();   // e(t) ready; also separates B(t-1) reads of part_s

        int j0 = jt * TJ;

        // --- bias partials: thread (j, quad); Wpb [d][n] via float4 pairs --
        {
            int j = tid & 63, quad = tid >> 6;
            float pb[NH];
            #pragma unroll
            for (int n=0;n<NH;n++) pb[n] = 0.f;
            const float4* er4 = (const float4*)(e_s + j*ROWF + quad*32);
            #pragma unroll
            for (int d4 = 0; d4 < 8; d4++) {
                float4 ev = er4[d4];
                const float* evp = (const float*)&ev;
                #pragma unroll
                for (int r = 0; r < 4; r++) {
                    const float* wrow = Wpb_s + (quad*32 + d4*4 + r)*NH;
                    float4 wA = *(const float4*)(wrow);
                    float4 wB = *(const float4*)(wrow + 4);
                    float e1 = evp[r];
                    pb[0] += e1*wA.x; pb[1] += e1*wA.y;
                    pb[2] += e1*wA.z; pb[3] += e1*wA.w;
                    pb[4] += e1*wB.x; pb[5] += e1*wB.y;
                    pb[6] += e1*wB.z; pb[7] += e1*wB.w;
                }
            }
            float* po = part_s + (quad*64 + j)*9;
            #pragma unroll
            for (int n=0;n<NH;n++) po[n] = pb[n];
        }
        __syncthreads();

        // --- full logits (2 heads per thread) -> logit_s[n][512] ---
        {
            int j = tid & 63, nb = tid >> 6;
            #pragma unroll
            for (int h = 0; h < 2; h++) {
                int n = nb + h*4;
                float bias = part_s[(0*64+j)*9+n] + part_s[(1*64+j)*9+n]
                           + part_s[(2*64+j)*9+n] + part_s[(3*64+j)*9+n];
                const float4* kr = (const float4*)(g_ks + ((b*NH+n)*LSEQ + j0 + j)*DS);
                float dot = 0.f;
                #pragma unroll
                for (int q4 = 0; q4 < 4; q4++) {
                    float4 kv = kr[q4];
                    const float* qq = qs_s + n*DS + q4*4;
                    dot += qq[0]*kv.x + qq[1]*kv.y + qq[2]*kv.z + qq[3]*kv.w;
                }
                const float4* kp = (const float4*)(g_kp + ((b*NH+n)*LSEQ + j0 + j)*12);
                float sq = 0.f;
                #pragma unroll
                for (int q4 = 0; q4 < 3; q4++) {
                    float4 kv = kp[q4];
                    const float* qq = qp_s + n*12 + q4*4;
                    float d0 = qq[0]-kv.x, d1 = qq[1]-kv.y, d2 = qq[2]-kv.z, d3 = qq[3]-kv.w;
                    sq += d0*d0 + d1*d1 + d2*d2 + d3*d3;
                }
                logit_s[n*LSEQ + j0 + j] = SCALE_TOTAL*(SCALE_SCALAR*dot + bias
                                    - 0.5f*SCALE_POINT*gamma_s[n]*sq);
            }
        }
        // loop-top __syncthreads covers B(t) -> A(t+1) part_s hazard
    }
    __syncthreads();

    // ---- one softmax per head (warp = head), normalize in place ----
    {
        int n = warp;
        float l[16];
        float m = -1e30f;
        #pragma unroll
        for (int k = 0; k < 16; k++) {
            l[k] = logit_s[n*LSEQ + lane + k*32];
            m = fmaxf(m, l[k]);
        }
        #pragma unroll
        for (int o = 16; o > 0; o >>= 1)
            m = fmaxf(m, __shfl_xor_sync(0xffffffffu, m, o));
        float s = 0.f;
        #pragma unroll
        for (int k = 0; k < 16; k++) { l[k] = __expf(l[k] - m); s += l[k]; }
        #pragma unroll
        for (int o = 16; o > 0; o >>= 1)
            s += __shfl_xor_sync(0xffffffffu, s, o);
        float inv = 1.f / s;
        #pragma unroll
        for (int k = 0; k < 16; k++)
            logit_s[n*LSEQ + lane + k*32] = l[k] * inv;
    }
    __syncthreads();

    // ---- normalized probs -> global (coalesced float4) ----
    {
        float4* gp4 = (float4*)(g_probs + (size_t)row * NH * LSEQ);
        #pragma unroll
        for (int k = 0; k < 4; k++) {
            int o = tid + k*256;
            gp4[o] = *(const float4*)&logit_s[o*4];
        }
    }

    // ---- out_s / out_p with normalized probs (warp = head) ----
    float acc = 0.f;
    {
        int n = warp;
        if (lane < 28) {
            const float* vb; int st;
            if (lane < 16) { vb = g_vs + ((size_t)(b*NH+n)*LSEQ)*DS + lane; st = DS; }
            else           { vb = g_vp + ((size_t)(b*NH+n)*LSEQ)*12 + (lane-16); st = 12; }
            const float* pr = logit_s + n*LSEQ;
            #pragma unroll 8
            for (int j = 0; j < LSEQ; j++) acc += pr[j] * vb[j*st];
        }
    }
    float* feat = g_feat + (size_t)row * NFEAT;
    if (lane < 16)      feat[warp*DS + lane] = acc;
    else if (lane < 28) op_s[warp*12 + (lane-16)] = acc;
    __syncthreads();

    if (tid < 32) {
        int n = tid >> 2, p = tid & 3;
        const float* rr = R + row*9;
        const float* tt = T + row*3;
        float o0 = op_s[n*12+p*3+0] - tt[0];
        float o1 = op_s[n*12+p*3+1] - tt[1];
        float o2 = op_s[n*12+p*3+2] - tt[2];
        float nsq = 0.f;
        #pragma unroll
        for (int c = 0; c < 3; c++) {
            float lc = o0*rr[c*3+0] + o1*rr[c*3+1] + o2*rr[c*3+2];
            feat[1152 + n*12 + p*3 + c] = lc;
            nsq += lc*lc;
        }
        feat[1248 + n*4 + p] = sqrtf(nsq);
    }
}

// ------ kernel 3b: out_pair = P @ E (streaming, probs in smem) -----------
#define K2_E0     0
#define K2_E1     8448
#define K2_P      16896          /* [n][512] = 4096 */
#define K2_FLOATS 20992

__global__ void __launch_bounds__(256) ipa_pair(const float* __restrict__ E)
{
    extern __shared__ float sm[];
    float* p_s = sm + K2_P;

    int row = blockIdx.x;
    int tid = threadIdx.x;
    int jl = tid >> 5, dl = tid & 31;

    unsigned sbase = (unsigned)__cvta_generic_to_shared(sm);
    const float* Ebi = E + (size_t)row * LSEQ * DPAIR;

    // prologue: tile 0 -> buffer 0
    {
        const float4* esrc = (const float4*)Ebi;
        #pragma unroll
        for (int it = 0; it < 8; it++) {
            int g = it*256 + tid;
            int j = g >> 5, d = (g & 31) * 4;
            cp_async16(sbase + (unsigned)((K2_E0 + j*ROWF + d) * 4), esrc + g);
        }
        asm volatile("cp.async.commit_group;");
    }

    // probs -> smem (coalesced)
    {
        const float4* gp4 = (const float4*)(g_probs + (size_t)row * NH * LSEQ);
        #pragma unroll
        for (int k = 0; k < 4; k++) {
            int o = tid + k*256;
            *(float4*)&p_s[o*4] = gp4[o];
        }
    }

    float acc[NH][4];
    #pragma unroll
    for (int n=0;n<NH;n++)
        #pragma unroll
        for (int c=0;c<4;c++) acc[n][c] = 0.f;

    for (int jt = 0; jt < LSEQ/TJ; jt++) {
        float* e_s = sm + ((jt & 1) ? K2_E1 : K2_E0);

        if (jt + 1 < LSEQ/TJ) {
            const float4* nsrc = (const float4*)(Ebi + (size_t)(jt+1)*TJ*DPAIR);
            unsigned bofs = (jt & 1) ? K2_E0 : K2_E1;
            #pragma unroll
            for (int it = 0; it < 8; it++) {
                int g = it*256 + tid;
                int j = g >> 5, d = (g & 31) * 4;
                cp_async16(sbase + (unsigned)((bofs + j*ROWF + d) * 4), nsrc + g);
            }
            asm volatile("cp.async.commit_group;");
            asm volatile("cp.async.wait_group 1;");
        } else {
            asm volatile("cp.async.wait_group 0;");
        }
        __syncthreads();

        int j0 = jt * TJ;
        #pragma unroll
        for (int jj = 0; jj < 8; jj++) {
            int j = jl*8 + jj;
            float4 ev = *(const float4*)(e_s + j*ROWF + dl*4);
            const float* pj = p_s + j0 + j;
            #pragma unroll
            for (int n=0;n<NH;n++) {
                float p = pj[n*LSEQ];
                acc[n][0] += p*ev.x; acc[n][1] += p*ev.y;
                acc[n][2] += p*ev.z; acc[n][3] += p*ev.w;
            }
        }
        __syncthreads();   // all reads done before next-iter prefetch reuses buffer
    }

    // cross-warp reduce via e buffer 0 (8192 floats fit in 8448)
    float* red = sm + K2_E0;
    #pragma unroll
    for (int n=0;n<NH;n++)
        *(float4*)(red + (jl*NH + n)*128 + dl*4) =
            make_float4(acc[n][0], acc[n][1], acc[n][2], acc[n][3]);
    __syncthreads();

    float* feat = g_feat + (size_t)row * NFEAT + 128;
    #pragma unroll
    for (int k = 0; k < 4; k++) {
        int o = tid + k*256;
        int n = o >> 7, d = o & 127;
        float s = 0.f;
        #pragma unroll
        for (int w = 0; w < 8; w++) s += red[(w*NH+n)*128 + d];
        feat[n*128 + d] = s;
    }
}

// ------------- kernel 4: output GEMM, 4-way split-K partials --------------
__global__ void __launch_bounds__(64) out_gemm_sk(const float* __restrict__ Wout)
{
    __shared__ float As[2][16*36];
    __shared__ float Bs[2][16*32];
    const int tid = threadIdx.x;
    const int tx = tid & 7, ty = tid >> 3;
    const int row0 = blockIdx.y * 32;
    const int col0 = blockIdx.x * 32;
    const int kbase = blockIdx.z * KSPLIT;

    const int a_m0 = tid >> 2, a_k4 = tid & 3;
    const int b_k0 = tid >> 3, b_n4 = tid & 7;

    ull acc2[4][2];
    #pragma unroll
    for (int i=0;i<4;i++) { acc2[i][0]=0ull; acc2[i][1]=0ull; }

    {
        #pragma unroll
        for (int s=0;s<2;s++) {
            int m = a_m0 + s*16;
            float4 v = *(const float4*)&g_feat[(size_t)(row0+m)*NFEAT + kbase + a_k4*4];
            #pragma unroll
            for (int u=0;u<4;u++) As[0][(a_k4*4+u)*36 + m] = ((const float*)&v)[u];
            int k = b_k0 + s*8;
            *(float4*)&Bs[0][k*32 + b_n4*4] =
                *(const float4*)&Wout[(size_t)(kbase+k)*DRES + col0 + b_n4*4];
        }
    }
    __syncthreads();

    const int KB = KSPLIT/16;
    for (int kb = 0; kb < KB; kb++) {
        int cur = kb & 1;
        float4 va[2], vb[2];
        bool has = (kb+1 < KB);
        if (has) {
            int k0 = kbase + (kb+1)*16;
            #pragma unroll
            for (int s=0;s<2;s++) {
                int m = a_m0 + s*16;
                va[s] = *(const float4*)&g_feat[(size_t)(row0+m)*NFEAT + k0 + a_k4*4];
                int k = b_k0 + s*8;
                vb[s] = *(const float4*)&Wout[(size_t)(k0+k)*DRES + col0 + b_n4*4];
            }
        }
        #pragma unroll
        for (int kk = 0; kk < 16; kk++) {
            float4 a = *(const float4*)&As[cur][kk*36 + ty*4];
            float4 b = *(const float4*)&Bs[cur][kk*32 + tx*4];
            ull b01 = pk2(b.x, b.y), b23 = pk2(b.z, b.w);
            const float* ap = (const float*)&a;
            #pragma unroll
            for (int i=0;i<4;i++) {
                ull aa = pk2(ap[i], ap[i]);
                acc2[i][0] = ffma2(aa, b01, acc2[i][0]);
                acc2[i][1] = ffma2(aa, b23, acc2[i][1]);
            }
        }
        if (has) {
            int nxt = cur ^ 1;
            #pragma unroll
            for (int s=0;s<2;s++) {
                int m = a_m0 + s*16;
                #pragma unroll
                for (int u=0;u<4;u++) As[nxt][(a_k4*4+u)*36 + m] = ((const float*)&va[s])[u];
                int k = b_k0 + s*8;
                *(float4*)&Bs[nxt][k*32 + b_n4*4] = vb[s];
            }
        }
        __syncthreads();
    }

    float* dst = g_opart + (size_t)blockIdx.z * NROW * DRES;
    #pragma unroll
    for (int i=0;i<4;i++) {
        int row = row0 + ty*4 + i;
        float2 u0 = up2(acc2[i][0]), u1 = up2(acc2[i][1]);
        float4 o; o.x = u0.x; o.y = u0.y; o.z = u1.x; o.w = u1.y;
        *(float4*)&dst[(size_t)row*DRES + col0 + tx*4] = o;
    }
}

__global__ void __launch_bounds__(256) out_reduce(
    const float* __restrict__ bout, float* __restrict__ out)
{
    const int STRIDE4 = NROW*DRES/4;
    int i4 = blockIdx.x * 256 + threadIdx.x;
    const float4* p = (const float4*)g_opart;
    float4 a = p[i4], b = p[STRIDE4 + i4], c = p[2*STRIDE4 + i4], d = p[3*STRIDE4 + i4];
    int col = (i4 * 4) % DRES;
    float4 bb = *(const float4*)&bout[col];
    float4 o;
    o.x = a.x + b.x + c.x + d.x + bb.x;
    o.y = a.y + b.y + c.y + d.y + bb.y;
    o.z = a.z + b.z + c.z + d.z + bb.z;
    o.w = a.w + b.w + c.w + d.w + bb.w;
    ((float4*)out)[i4] = o;
}

// ---------------- launch ----------------
extern "C" void kernel_launch(void* const* d_in, const int* in_sizes, int n_in,
                              void* d_out, int out_size)
{
    const float* x     = (const float*)d_in[0];
    const float* e     = (const float*)d_in[1];
    const float* r     = (const float*)d_in[2];
    const float* t     = (const float*)d_in[3];
    const float* Wqs   = (const float*)d_in[4];
    const float* Wks   = (const float*)d_in[5];
    const float* Wvs   = (const float*)d_in[6];
    const float* Wpb   = (const float*)d_in[7];
    const float* Wqp   = (const float*)d_in[8];
    const float* Wkp   = (const float*)d_in[9];
    const float* Wvp   = (const float*)d_in[10];
    const float* gamma = (const float*)d_in[11];
    const float* Wout  = (const float*)d_in[12];
    const float* bout  = (const float*)d_in[13];
    float* out = (float*)d_out;

    proj_gemm<<<dim3(21, 32), 64>>>(x, Wqs, Wks, Wvs, Wqp, Wkp, Wvp);
    point_transform<<<NROW, 96>>>(r, t);

    cudaFuncSetAttribute(ipa_logits, cudaFuncAttributeMaxDynamicSharedMemorySize,
                         K1_FLOATS * (int)sizeof(float));
    ipa_logits<<<NROW, 256, K1_FLOATS * sizeof(float)>>>(e, r, t, Wpb, gamma);

    cudaFuncSetAttribute(ipa_pair, cudaFuncAttributeMaxDynamicSharedMemorySize,
                         K2_FLOATS * (int)sizeof(float));
    ipa_pair<<<NROW, 256, K2_FLOATS * sizeof(float)>>>(e);

    out_gemm_sk<<<dim3(12, 32, NSPLIT), 64>>>(Wout);
    out_reduce<<<NROW*DRES/4/256, 256>>>(bout, out);
}

// round 13
// speedup vs baseline: 1.0799x; 1.0799x over previous
#include <cuda_runtime.h>
#include <math.h>

#define NH      8
#define LSEQ    512
#define DRES    384
#define DPAIR   128
#define DS      16
#define TJ      64
#define ROWF    132
#define NROW    1024
#define NFEAT   1280
#define NSPLIT  4
#define KSPLIT  (NFEAT/NSPLIT)

#define SCALE_SCALAR 0.25f
#define SCALE_POINT  0.2357022603955158f   /* 18^-0.5 */
#define SCALE_TOTAL  0.5773502691896258f   /* 3^-0.5  */

typedef unsigned long long ull;

__device__ __forceinline__ ull pk2(float x, float y) {
    ull r; asm("mov.b64 %0,{%1,%2};" : "=l"(r) : "f"(x), "f"(y)); return r;
}
__device__ __forceinline__ ull ffma2(ull a, ull b, ull c) {
    ull d; asm("fma.rn.f32x2 %0,%1,%2,%3;" : "=l"(d) : "l"(a), "l"(b), "l"(c)); return d;
}
__device__ __forceinline__ float2 up2(ull v) {
    float2 r; asm("mov.b64 {%0,%1},%2;" : "=f"(r.x), "=f"(r.y) : "l"(v)); return r;
}
__device__ __forceinline__ void cp_async16(unsigned smem_addr, const void* gptr) {
    asm volatile("cp.async.cg.shared.global [%0], [%1], 16;"
                 :: "r"(smem_addr), "l"(gptr));
}

// ---------------- scratch (device globals; no allocation) ----------------
__device__ float g_qs[2*NH*LSEQ*DS];
__device__ float g_ks[2*NH*LSEQ*DS];
__device__ float g_vs[2*NH*LSEQ*DS];
__device__ float g_qp[2*NH*LSEQ*12];
__device__ float g_kp[2*NH*LSEQ*12];
__device__ float g_vp[2*NH*LSEQ*12];
__device__ float g_praw[NROW*288];
__device__ float g_feat[(size_t)NROW*NFEAT];
__device__ float g_opart[(size_t)NSPLIT*NROW*DRES];
__device__ float g_probs[(size_t)NROW*NH*LSEQ];
__device__ float g_bias[(size_t)NROW*NH*LSEQ];

// ---------------- kernel 1: projection GEMM ------------------------------
__global__ void __launch_bounds__(64) proj_gemm(
    const float* __restrict__ X,
    const float* __restrict__ Wqs, const float* __restrict__ Wks,
    const float* __restrict__ Wvs, const float* __restrict__ Wqp,
    const float* __restrict__ Wkp, const float* __restrict__ Wvp)
{
    __shared__ float As[2][16*36];
    __shared__ float Bs[2][16*32];
    const int tid = threadIdx.x;
    const int tx = tid & 7, ty = tid >> 3;
    const int row0 = blockIdx.y * 32;
    const int col0 = blockIdx.x * 32;

    const float* Wseg; int segw, cl0;
    if (col0 < 384) {
        int sg = col0 >> 7;
        Wseg = (sg==0) ? Wqs : ((sg==1) ? Wks : Wvs);
        segw = 128; cl0 = col0 & 127;
    } else {
        int c2 = col0 - 384; int sg = c2 / 96;
        Wseg = (sg==0) ? Wqp : ((sg==1) ? Wkp : Wvp);
        segw = 96; cl0 = c2 - sg*96;
    }

    const int a_m0 = tid >> 2, a_k4 = tid & 3;
    const int b_k0 = tid >> 3, b_n4 = tid & 7;

    float acc[4][4];
    #pragma unroll
    for (int i=0;i<4;i++)
        #pragma unroll
        for (int j=0;j<4;j++) acc[i][j]=0.f;

    {
        #pragma unroll
        for (int s=0;s<2;s++) {
            int m = a_m0 + s*16;
            float4 v = *(const float4*)&X[(size_t)(row0+m)*DRES + a_k4*4];
            #pragma unroll
            for (int u=0;u<4;u++) As[0][(a_k4*4+u)*36 + m] = ((const float*)&v)[u];
            int k = b_k0 + s*8;
            *(float4*)&Bs[0][k*32 + b_n4*4] =
                *(const float4*)&Wseg[(size_t)k*segw + cl0 + b_n4*4];
        }
    }
    __syncthreads();

    const int KB = DRES/16;
    for (int kb = 0; kb < KB; kb++) {
        int cur = kb & 1;
        float4 va[2], vb[2];
        bool has = (kb+1 < KB);
        if (has) {
            int k0 = (kb+1)*16;
            #pragma unroll
            for (int s=0;s<2;s++) {
                int m = a_m0 + s*16;
                va[s] = *(const float4*)&X[(size_t)(row0+m)*DRES + k0 + a_k4*4];
                int k = b_k0 + s*8;
                vb[s] = *(const float4*)&Wseg[(size_t)(k0+k)*segw + cl0 + b_n4*4];
            }
        }
        #pragma unroll
        for (int kk = 0; kk < 16; kk++) {
            float4 a = *(const float4*)&As[cur][kk*36 + ty*4];
            float4 b = *(const float4*)&Bs[cur][kk*32 + tx*4];
            const float* ap = (const float*)&a;
            const float* bp = (const float*)&b;
            #pragma unroll
            for (int i=0;i<4;i++)
                #pragma unroll
                for (int j=0;j<4;j++) acc[i][j] += ap[i]*bp[j];
        }
        if (has) {
            int nxt = cur ^ 1;
            #pragma unroll
            for (int s=0;s<2;s++) {
                int m = a_m0 + s*16;
                #pragma unroll
                for (int u=0;u<4;u++) As[nxt][(a_k4*4+u)*36 + m] = ((const float*)&va[s])[u];
                int k = b_k0 + s*8;
                *(float4*)&Bs[nxt][k*32 + b_n4*4] = vb[s];
            }
        }
        __syncthreads();
    }

    #pragma unroll
    for (int i=0;i<4;i++) {
        int row = row0 + ty*4 + i;
        int b = row >> 9, l = row & 511;
        #pragma unroll
        for (int j=0;j<4;j++) {
            int col = col0 + tx*4 + j;
            float v = acc[i][j];
            if (col < 384) {
                int sg = col >> 7;
                int n = (col & 127) >> 4, d = col & 15;
                float* dst = (sg==0) ? g_qs : ((sg==1) ? g_ks : g_vs);
                dst[(((b*NH)+n)*LSEQ + l)*DS + d] = v;
            } else {
                g_praw[row*288 + (col-384)] = v;
            }
        }
    }
}

// ---------------- kernel 2: euclid transform of projected points ---------
__global__ void point_transform(const float* __restrict__ R, const float* __restrict__ T)
{
    int row = blockIdx.x;
    int b = row >> 9, l = row & 511;
    int t = threadIdx.x;
    if (t >= 96) return;
    int tensor = t / 32, idx = t % 32;
    int n = idx >> 2, p = idx & 3;
    const float* xr = &g_praw[row*288 + tensor*96 + n*12 + p*3];
    const float* rr = &R[row*9];
    const float* tt = &T[row*3];
    float x0 = xr[0], x1 = xr[1], x2 = xr[2];
    float* dst = ((tensor==0) ? g_qp : ((tensor==1) ? g_kp : g_vp))
               + (((b*NH)+n)*LSEQ + l)*12 + p*3;
    #pragma unroll
    for (int c = 0; c < 3; c++)
        dst[c] = x0*rr[0*3+c] + x1*rr[1*3+c] + x2*rr[2*3+c] + tt[c];
}

// -------- kernel 3a: bias = e @ Wpb, streaming (pair-kernel clone) --------
#define BK_E0     0
#define BK_E1     8448
#define BK_WPB    16896
#define BK_PART   17920          /* 256*9 = 2304 */
#define BK_FLOATS 20224

__global__ void __launch_bounds__(256) ipa_bias(
    const float* __restrict__ E, const float* __restrict__ Wpb)
{
    extern __shared__ float sm[];
    float* Wpb_s  = sm + BK_WPB;
    float* part_s = sm + BK_PART;

    int row = blockIdx.x;
    int tid = threadIdx.x;

    unsigned sbase = (unsigned)__cvta_generic_to_shared(sm);
    const float* Ebi = E + (size_t)row * LSEQ * DPAIR;

    {
        const float4* esrc = (const float4*)Ebi;
        #pragma unroll
        for (int it = 0; it < 8; it++) {
            int g = it*256 + tid;
            int j = g >> 5, d = (g & 31) * 4;
            cp_async16(sbase + (unsigned)((BK_E0 + j*ROWF + d) * 4), esrc + g);
        }
        asm volatile("cp.async.commit_group;");
    }

    for (int k = tid; k < DPAIR*NH; k += 256) Wpb_s[k] = Wpb[k];

    float* gb = g_bias + (size_t)row * NH * LSEQ;

    for (int jt = 0; jt < LSEQ/TJ; jt++) {
        float* e_s = sm + ((jt & 1) ? BK_E1 : BK_E0);

        if (jt + 1 < LSEQ/TJ) {
            const float4* nsrc = (const float4*)(Ebi + (size_t)(jt+1)*TJ*DPAIR);
            unsigned bofs = (jt & 1) ? BK_E0 : BK_E1;
            #pragma unroll
            for (int it = 0; it < 8; it++) {
                int g = it*256 + tid;
                int j = g >> 5, d = (g & 31) * 4;
                cp_async16(sbase + (unsigned)((bofs + j*ROWF + d) * 4), nsrc + g);
            }
            asm volatile("cp.async.commit_group;");
            asm volatile("cp.async.wait_group 1;");
        } else {
            asm volatile("cp.async.wait_group 0;");
        }
        __syncthreads();   // e ready; also part_s read(t-1) vs write(t) hazard

        int j0 = jt * TJ;

        // phase A: partial dot over 32 dims
        {
            int j = tid & 63, quad = tid >> 6;
            float pb[NH];
            #pragma unroll
            for (int n=0;n<NH;n++) pb[n] = 0.f;
            const float4* er4 = (const float4*)(e_s + j*ROWF + quad*32);
            #pragma unroll
            for (int d4 = 0; d4 < 8; d4++) {
                float4 ev = er4[d4];
                const float* evp = (const float*)&ev;
                #pragma unroll
                for (int r = 0; r < 4; r++) {
                    const float* wrow = Wpb_s + (quad*32 + d4*4 + r)*NH;
                    float4 wA = *(const float4*)(wrow);
                    float4 wB = *(const float4*)(wrow + 4);
                    float e1 = evp[r];
                    pb[0] += e1*wA.x; pb[1] += e1*wA.y;
                    pb[2] += e1*wA.z; pb[3] += e1*wA.w;
                    pb[4] += e1*wB.x; pb[5] += e1*wB.y;
                    pb[6] += e1*wB.z; pb[7] += e1*wB.w;
                }
            }
            float* po = part_s + (quad*64 + j)*9;
            #pragma unroll
            for (int n=0;n<NH;n++) po[n] = pb[n];
        }
        __syncthreads();

        // phase B: reduce 4 quads, write bias to global (coalesced per head)
        {
            int j = tid & 63, nb = tid >> 6;
            #pragma unroll
            for (int h = 0; h < 2; h++) {
                int n = nb + h*4;
                float bias = part_s[(0*64+j)*9+n] + part_s[(1*64+j)*9+n]
                           + part_s[(2*64+j)*9+n] + part_s[(3*64+j)*9+n];
                gb[n*LSEQ + j0 + j] = bias;
            }
        }
        // loop-top sync covers part_s write(t+1) vs read(t)
    }
}

// -------- kernel 3b: logits + softmax + out_s/out_p (no e access) --------
__global__ void __launch_bounds__(256) ipa_logits(
    const float* __restrict__ R, const float* __restrict__ T,
    const float* __restrict__ gamma)
{
    __shared__ float qs_s[128];
    __shared__ float qp_s[96];
    __shared__ float prob_s[NH*LSEQ];
    __shared__ float op_s[96];

    int row = blockIdx.x;
    int b = row >> 9, i = row & 511;
    int tid = threadIdx.x;
    int warp = tid >> 5, lane = tid & 31;

    if (tid < 128) { int n = tid >> 4, d = tid & 15;
        qs_s[tid] = g_qs[((b*NH+n)*LSEQ + i)*DS + d]; }
    if (tid < 96)  { int n = tid/12, pc = tid - n*12;
        qp_s[tid] = g_qp[((b*NH+n)*LSEQ + i)*12 + pc]; }
    __syncthreads();

    int n = warp;
    float gam = gamma[n];
    const float* gb = g_bias + (size_t)row * NH * LSEQ + n*LSEQ;

    // --- 16 logits per lane, straight into registers ---
    float l[16];
    #pragma unroll
    for (int k = 0; k < 16; k++) {
        int j = lane + k*32;
        const float4* kr = (const float4*)(g_ks + ((b*NH+n)*LSEQ + j)*DS);
        float dot = 0.f;
        #pragma unroll
        for (int q4 = 0; q4 < 4; q4++) {
            float4 kv = kr[q4];
            const float* qq = qs_s + n*DS + q4*4;
            dot += qq[0]*kv.x + qq[1]*kv.y + qq[2]*kv.z + qq[3]*kv.w;
        }
        const float4* kp = (const float4*)(g_kp + ((b*NH+n)*LSEQ + j)*12);
        float sq = 0.f;
        #pragma unroll
        for (int q4 = 0; q4 < 3; q4++) {
            float4 kv = kp[q4];
            const float* qq = qp_s + n*12 + q4*4;
            float d0 = qq[0]-kv.x, d1 = qq[1]-kv.y, d2 = qq[2]-kv.z, d3 = qq[3]-kv.w;
            sq += d0*d0 + d1*d1 + d2*d2 + d3*d3;
        }
        l[k] = SCALE_TOTAL*(SCALE_SCALAR*dot + gb[j] - 0.5f*SCALE_POINT*gam*sq);
    }

    // --- softmax in registers (warp = head) ---
    float m = -1e30f;
    #pragma unroll
    for (int k = 0; k < 16; k++) m = fmaxf(m, l[k]);
    #pragma unroll
    for (int o = 16; o > 0; o >>= 1)
        m = fmaxf(m, __shfl_xor_sync(0xffffffffu, m, o));
    float s = 0.f;
    #pragma unroll
    for (int k = 0; k < 16; k++) { l[k] = __expf(l[k] - m); s += l[k]; }
    #pragma unroll
    for (int o = 16; o > 0; o >>= 1)
        s += __shfl_xor_sync(0xffffffffu, s, o);
    float inv = 1.f / s;

    // --- probs -> smem (own head) + global (coalesced 128B stores) ---
    float* pr = prob_s + n*LSEQ;
    float* gp = g_probs + (size_t)row * NH * LSEQ + n*LSEQ;
    #pragma unroll
    for (int k = 0; k < 16; k++) {
        int j = lane + k*32;
        float p = l[k] * inv;
        pr[j] = p;
        gp[j] = p;
    }
    __syncwarp();

    // --- out_s / out_p with normalized probs ---
    float acc = 0.f;
    if (lane < 28) {
        const float* vb; int st;
        if (lane < 16) { vb = g_vs + ((size_t)(b*NH+n)*LSEQ)*DS + lane; st = DS; }
        else           { vb = g_vp + ((size_t)(b*NH+n)*LSEQ)*12 + (lane-16); st = 12; }
        #pragma unroll 8
        for (int j = 0; j < LSEQ; j++) acc += pr[j] * vb[j*st];
    }
    float* feat = g_feat + (size_t)row * NFEAT;
    if (lane < 16)      feat[warp*DS + lane] = acc;
    else if (lane < 28) op_s[warp*12 + (lane-16)] = acc;
    __syncthreads();

    if (tid < 32) {
        int nn = tid >> 2, p = tid & 3;
        const float* rr = R + row*9;
        const float* tt = T + row*3;
        float o0 = op_s[nn*12+p*3+0] - tt[0];
        float o1 = op_s[nn*12+p*3+1] - tt[1];
        float o2 = op_s[nn*12+p*3+2] - tt[2];
        float nsq = 0.f;
        #pragma unroll
        for (int c = 0; c < 3; c++) {
            float lc = o0*rr[c*3+0] + o1*rr[c*3+1] + o2*rr[c*3+2];
            feat[1152 + nn*12 + p*3 + c] = lc;
            nsq += lc*lc;
        }
        feat[1248 + nn*4 + p] = sqrtf(nsq);
    }
}

// ------ kernel 3c: out_pair = P @ E (streaming, probs in smem) -----------
#define K2_E0     0
#define K2_E1     8448
#define K2_P      16896          /* [n][512] = 4096 */
#define K2_FLOATS 20992

__global__ void __launch_bounds__(256) ipa_pair(const float* __restrict__ E)
{
    extern __shared__ float sm[];
    float* p_s = sm + K2_P;

    int row = blockIdx.x;
    int tid = threadIdx.x;
    int jl = tid >> 5, dl = tid & 31;

    unsigned sbase = (unsigned)__cvta_generic_to_shared(sm);
    const float* Ebi = E + (size_t)row * LSEQ * DPAIR;

    {
        const float4* esrc = (const float4*)Ebi;
        #pragma unroll
        for (int it = 0; it < 8; it++) {
            int g = it*256 + tid;
            int j = g >> 5, d = (g & 31) * 4;
            cp_async16(sbase + (unsigned)((K2_E0 + j*ROWF + d) * 4), esrc + g);
        }
        asm volatile("cp.async.commit_group;");
    }

    {
        const float4* gp4 = (const float4*)(g_probs + (size_t)row * NH * LSEQ);
        #pragma unroll
        for (int k = 0; k < 4; k++) {
            int o = tid + k*256;
            *(float4*)&p_s[o*4] = gp4[o];
        }
    }

    float acc[NH][4];
    #pragma unroll
    for (int n=0;n<NH;n++)
        #pragma unroll
        for (int c=0;c<4;c++) acc[n][c] = 0.f;

    for (int jt = 0; jt < LSEQ/TJ; jt++) {
        float* e_s = sm + ((jt & 1) ? K2_E1 : K2_E0);

        if (jt + 1 < LSEQ/TJ) {
            const float4* nsrc = (const float4*)(Ebi + (size_t)(jt+1)*TJ*DPAIR);
            unsigned bofs = (jt & 1) ? K2_E0 : K2_E1;
            #pragma unroll
            for (int it = 0; it < 8; it++) {
                int g = it*256 + tid;
                int j = g >> 5, d = (g & 31) * 4;
                cp_async16(sbase + (unsigned)((bofs + j*ROWF + d) * 4), nsrc + g);
            }
            asm volatile("cp.async.commit_group;");
            asm volatile("cp.async.wait_group 1;");
        } else {
            asm volatile("cp.async.wait_group 0;");
        }
        __syncthreads();

        int j0 = jt * TJ;
        #pragma unroll
        for (int jj = 0; jj < 8; jj++) {
            int j = jl*8 + jj;
            float4 ev = *(const float4*)(e_s + j*ROWF + dl*4);
            const float* pj = p_s + j0 + j;
            #pragma unroll
            for (int n=0;n<NH;n++) {
                float p = pj[n*LSEQ];
                acc[n][0] += p*ev.x; acc[n][1] += p*ev.y;
                acc[n][2] += p*ev.z; acc[n][3] += p*ev.w;
            }
        }
        __syncthreads();
    }

    float* red = sm + K2_E0;
    #pragma unroll
    for (int n=0;n<NH;n++)
        *(float4*)(red + (jl*NH + n)*128 + dl*4) =
            make_float4(acc[n][0], acc[n][1], acc[n][2], acc[n][3]);
    __syncthreads();

    float* feat = g_feat + (size_t)row * NFEAT + 128;
    #pragma unroll
    for (int k = 0; k < 4; k++) {
        int o = tid + k*256;
        int n = o >> 7, d = o & 127;
        float s = 0.f;
        #pragma unroll
        for (int w = 0; w < 8; w++) s += red[(w*NH+n)*128 + d];
        feat[n*128 + d] = s;
    }
}

// ------------- kernel 4: output GEMM, 4-way split-K partials --------------
__global__ void __launch_bounds__(64) out_gemm_sk(const float* __restrict__ Wout)
{
    __shared__ float As[2][16*36];
    __shared__ float Bs[2][16*32];
    const int tid = threadIdx.x;
    const int tx = tid & 7, ty = tid >> 3;
    const int row0 = blockIdx.y * 32;
    const int col0 = blockIdx.x * 32;
    const int kbase = blockIdx.z * KSPLIT;

    const int a_m0 = tid >> 2, a_k4 = tid & 3;
    const int b_k0 = tid >> 3, b_n4 = tid & 7;

    ull acc2[4][2];
    #pragma unroll
    for (int i=0;i<4;i++) { acc2[i][0]=0ull; acc2[i][1]=0ull; }

    {
        #pragma unroll
        for (int s=0;s<2;s++) {
            int m = a_m0 + s*16;
            float4 v = *(const float4*)&g_feat[(size_t)(row0+m)*NFEAT + kbase + a_k4*4];
            #pragma unroll
            for (int u=0;u<4;u++) As[0][(a_k4*4+u)*36 + m] = ((const float*)&v)[u];
            int k = b_k0 + s*8;
            *(float4*)&Bs[0][k*32 + b_n4*4] =
                *(const float4*)&Wout[(size_t)(kbase+k)*DRES + col0 + b_n4*4];
        }
    }
    __syncthreads();

    const int KB = KSPLIT/16;
    for (int kb = 0; kb < KB; kb++) {
        int cur = kb & 1;
        float4 va[2], vb[2];
        bool has = (kb+1 < KB);
        if (has) {
            int k0 = kbase + (kb+1)*16;
            #pragma unroll
            for (int s=0;s<2;s++) {
                int m = a_m0 + s*16;
                va[s] = *(const float4*)&g_feat[(size_t)(row0+m)*NFEAT + k0 + a_k4*4];
                int k = b_k0 + s*8;
                vb[s] = *(const float4*)&Wout[(size_t)(k0+k)*DRES + col0 + b_n4*4];
            }
        }
        #pragma unroll
        for (int kk = 0; kk < 16; kk++) {
            float4 a = *(const float4*)&As[cur][kk*36 + ty*4];
            float4 b = *(const float4*)&Bs[cur][kk*32 + tx*4];
            ull b01 = pk2(b.x, b.y), b23 = pk2(b.z, b.w);
            const float* ap = (const float*)&a;
            #pragma unroll
            for (int i=0;i<4;i++) {
                ull aa = pk2(ap[i], ap[i]);
                acc2[i][0] = ffma2(aa, b01, acc2[i][0]);
                acc2[i][1] = ffma2(aa, b23, acc2[i][1]);
            }
        }
        if (has) {
            int nxt = cur ^ 1;
            #pragma unroll
            for (int s=0;s<2;s++) {
                int m = a_m0 + s*16;
                #pragma unroll
                for (int u=0;u<4;u++) As[nxt][(a_k4*4+u)*36 + m] = ((const float*)&va[s])[u];
                int k = b_k0 + s*8;
                *(float4*)&Bs[nxt][k*32 + b_n4*4] = vb[s];
            }
        }
        __syncthreads();
    }

    float* dst = g_opart + (size_t)blockIdx.z * NROW * DRES;
    #pragma unroll
    for (int i=0;i<4;i++) {
        int row = row0 + ty*4 + i;
        float2 u0 = up2(acc2[i][0]), u1 = up2(acc2[i][1]);
        float4 o; o.x = u0.x; o.y = u0.y; o.z = u1.x; o.w = u1.y;
        *(float4*)&dst[(size_t)row*DRES + col0 + tx*4] = o;
    }
}

__global__ void __launch_bounds__(256) out_reduce(
    const float* __restrict__ bout, float* __restrict__ out)
{
    const int STRIDE4 = NROW*DRES/4;
    int i4 = blockIdx.x * 256 + threadIdx.x;
    const float4* p = (const float4*)g_opart;
    float4 a = p[i4], b = p[STRIDE4 + i4], c = p[2*STRIDE4 + i4], d = p[3*STRIDE4 + i4];
    int col = (i4 * 4) % DRES;
    float4 bb = *(const float4*)&bout[col];
    float4 o;
    o.x = a.x + b.x + c.x + d.x + bb.x;
    o.y = a.y + b.y + c.y + d.y + bb.y;
    o.z = a.z + b.z + c.z + d.z + bb.z;
    o.w = a.w + b.w + c.w + d.w + bb.w;
    ((float4*)out)[i4] = o;
}

// ---------------- launch ----------------
extern "C" void kernel_launch(void* const* d_in, const int* in_sizes, int n_in,
                              void* d_out, int out_size)
{
    const float* x     = (const float*)d_in[0];
    const float* e     = (const float*)d_in[1];
    const float* r     = (const float*)d_in[2];
    const float* t     = (const float*)d_in[3];
    const float* Wqs   = (const float*)d_in[4];
    const float* Wks   = (const float*)d_in[5];
    const float* Wvs   = (const float*)d_in[6];
    const float* Wpb   = (const float*)d_in[7];
    const float* Wqp   = (const float*)d_in[8];
    const float* Wkp   = (const float*)d_in[9];
    const float* Wvp   = (const float*)d_in[10];
    const float* gamma = (const float*)d_in[11];
    const float* Wout  = (const float*)d_in[12];
    const float* bout  = (const float*)d_in[13];
    float* out = (float*)d_out;

    proj_gemm<<<dim3(21, 32), 64>>>(x, Wqs, Wks, Wvs, Wqp, Wkp, Wvp);
    point_transform<<<NROW, 96>>>(r, t);

    cudaFuncSetAttribute(ipa_bias, cudaFuncAttributeMaxDynamicSharedMemorySize,
                         BK_FLOATS * (int)sizeof(float));
    ipa_bias<<<NROW, 256, BK_FLOATS * sizeof(float)>>>(e, Wpb);

    ipa_logits<<<NROW, 256>>>(r, t, gamma);

    cudaFuncSetAttribute(ipa_pair, cudaFuncAttributeMaxDynamicSharedMemorySize,
                         K2_FLOATS * (int)sizeof(float));
    ipa_pair<<<NROW, 256, K2_FLOATS * sizeof(float)>>>(e);

    out_gemm_sk<<<dim3(12, 32, NSPLIT), 64>>>(Wout);
    out_reduce<<<NROW*DRES/4/256, 256>>>(bout, out);
}

// round 14
// speedup vs baseline: 1.2248x; 1.1342x over previous
#include <cuda_runtime.h>
#include <math.h>

#define NH      8
#define LSEQ    512
#define DRES    384
#define DPAIR   128
#define DS      16
#define TJ      64
#define ROWF    132
#define NROW    1024
#define NFEAT   1280
#define NSPLIT  4
#define KSPLIT  (NFEAT/NSPLIT)

#define SCALE_SCALAR 0.25f
#define SCALE_POINT  0.2357022603955158f   /* 18^-0.5 */
#define SCALE_TOTAL  0.5773502691896258f   /* 3^-0.5  */

typedef unsigned long long ull;

__device__ __forceinline__ ull pk2(float x, float y) {
    ull r; asm("mov.b64 %0,{%1,%2};" : "=l"(r) : "f"(x), "f"(y)); return r;
}
__device__ __forceinline__ ull ffma2(ull a, ull b, ull c) {
    ull d; asm("fma.rn.f32x2 %0,%1,%2,%3;" : "=l"(d) : "l"(a), "l"(b), "l"(c)); return d;
}
__device__ __forceinline__ float2 up2(ull v) {
    float2 r; asm("mov.b64 {%0,%1},%2;" : "=f"(r.x), "=f"(r.y) : "l"(v)); return r;
}
__device__ __forceinline__ void cp_async16(unsigned smem_addr, const void* gptr) {
    asm volatile("cp.async.cg.shared.global [%0], [%1], 16;"
                 :: "r"(smem_addr), "l"(gptr));
}

// ---------------- scratch (device globals; no allocation) ----------------
__device__ float g_qs[2*NH*LSEQ*DS];
__device__ float g_ks[2*NH*LSEQ*DS];
__device__ float g_vs[2*NH*LSEQ*DS];
__device__ float g_qp[2*NH*LSEQ*12];
__device__ float g_kp[2*NH*LSEQ*12];
__device__ float g_vp[2*NH*LSEQ*12];
__device__ float g_praw[NROW*288];
__device__ float g_feat[(size_t)NROW*NFEAT];
__device__ float g_opart[(size_t)NSPLIT*NROW*DRES];
__device__ float g_probs[(size_t)NROW*NH*LSEQ];
__device__ float g_bias[(size_t)NROW*NH*LSEQ];

// ---------------- kernel 1: projection GEMM ------------------------------
__global__ void __launch_bounds__(64) proj_gemm(
    const float* __restrict__ X,
    const float* __restrict__ Wqs, const float* __restrict__ Wks,
    const float* __restrict__ Wvs, const float* __restrict__ Wqp,
    const float* __restrict__ Wkp, const float* __restrict__ Wvp)
{
    __shared__ float As[2][16*36];
    __shared__ float Bs[2][16*32];
    const int tid = threadIdx.x;
    const int tx = tid & 7, ty = tid >> 3;
    const int row0 = blockIdx.y * 32;
    const int col0 = blockIdx.x * 32;

    const float* Wseg; int segw, cl0;
    if (col0 < 384) {
        int sg = col0 >> 7;
        Wseg = (sg==0) ? Wqs : ((sg==1) ? Wks : Wvs);
        segw = 128; cl0 = col0 & 127;
    } else {
        int c2 = col0 - 384; int sg = c2 / 96;
        Wseg = (sg==0) ? Wqp : ((sg==1) ? Wkp : Wvp);
        segw = 96; cl0 = c2 - sg*96;
    }

    const int a_m0 = tid >> 2, a_k4 = tid & 3;
    const int b_k0 = tid >> 3, b_n4 = tid & 7;

    float acc[4][4];
    #pragma unroll
    for (int i=0;i<4;i++)
        #pragma unroll
        for (int j=0;j<4;j++) acc[i][j]=0.f;

    {
        #pragma unroll
        for (int s=0;s<2;s++) {
            int m = a_m0 + s*16;
            float4 v = *(const float4*)&X[(size_t)(row0+m)*DRES + a_k4*4];
            #pragma unroll
            for (int u=0;u<4;u++) As[0][(a_k4*4+u)*36 + m] = ((const float*)&v)[u];
            int k = b_k0 + s*8;
            *(float4*)&Bs[0][k*32 + b_n4*4] =
                *(const float4*)&Wseg[(size_t)k*segw + cl0 + b_n4*4];
        }
    }
    __syncthreads();

    const int KB = DRES/16;
    for (int kb = 0; kb < KB; kb++) {
        int cur = kb & 1;
        float4 va[2], vb[2];
        bool has = (kb+1 < KB);
        if (has) {
            int k0 = (kb+1)*16;
            #pragma unroll
            for (int s=0;s<2;s++) {
                int m = a_m0 + s*16;
                va[s] = *(const float4*)&X[(size_t)(row0+m)*DRES + k0 + a_k4*4];
                int k = b_k0 + s*8;
                vb[s] = *(const float4*)&Wseg[(size_t)(k0+k)*segw + cl0 + b_n4*4];
            }
        }
        #pragma unroll
        for (int kk = 0; kk < 16; kk++) {
            float4 a = *(const float4*)&As[cur][kk*36 + ty*4];
            float4 b = *(const float4*)&Bs[cur][kk*32 + tx*4];
            const float* ap = (const float*)&a;
            const float* bp = (const float*)&b;
            #pragma unroll
            for (int i=0;i<4;i++)
                #pragma unroll
                for (int j=0;j<4;j++) acc[i][j] += ap[i]*bp[j];
        }
        if (has) {
            int nxt = cur ^ 1;
            #pragma unroll
            for (int s=0;s<2;s++) {
                int m = a_m0 + s*16;
                #pragma unroll
                for (int u=0;u<4;u++) As[nxt][(a_k4*4+u)*36 + m] = ((const float*)&va[s])[u];
                int k = b_k0 + s*8;
                *(float4*)&Bs[nxt][k*32 + b_n4*4] = vb[s];
            }
        }
        __syncthreads();
    }

    #pragma unroll
    for (int i=0;i<4;i++) {
        int row = row0 + ty*4 + i;
        int b = row >> 9, l = row & 511;
        #pragma unroll
        for (int j=0;j<4;j++) {
            int col = col0 + tx*4 + j;
            float v = acc[i][j];
            if (col < 384) {
                int sg = col >> 7;
                int n = (col & 127) >> 4, d = col & 15;
                float* dst = (sg==0) ? g_qs : ((sg==1) ? g_ks : g_vs);
                dst[(((b*NH)+n)*LSEQ + l)*DS + d] = v;
            } else {
                g_praw[row*288 + (col-384)] = v;
            }
        }
    }
}

// ---------------- kernel 2: euclid transform of projected points ---------
__global__ void point_transform(const float* __restrict__ R, const float* __restrict__ T)
{
    int row = blockIdx.x;
    int b = row >> 9, l = row & 511;
    int t = threadIdx.x;
    if (t >= 96) return;
    int tensor = t / 32, idx = t % 32;
    int n = idx >> 2, p = idx & 3;
    const float* xr = &g_praw[row*288 + tensor*96 + n*12 + p*3];
    const float* rr = &R[row*9];
    const float* tt = &T[row*3];
    float x0 = xr[0], x1 = xr[1], x2 = xr[2];
    float* dst = ((tensor==0) ? g_qp : ((tensor==1) ? g_kp : g_vp))
               + (((b*NH)+n)*LSEQ + l)*12 + p*3;
    #pragma unroll
    for (int c = 0; c < 3; c++)
        dst[c] = x0*rr[0*3+c] + x1*rr[1*3+c] + x2*rr[2*3+c] + tt[c];
}

// -------- kernel 3a: bias = e @ Wpb, streaming (pair-kernel clone) --------
#define BK_E0     0
#define BK_E1     8448
#define BK_WPB    16896
#define BK_PART   17920          /* 256*9 = 2304 */
#define BK_FLOATS 20224

__global__ void __launch_bounds__(256) ipa_bias(
    const float* __restrict__ E, const float* __restrict__ Wpb)
{
    extern __shared__ float sm[];
    float* Wpb_s  = sm + BK_WPB;
    float* part_s = sm + BK_PART;

    int row = blockIdx.x;
    int tid = threadIdx.x;

    unsigned sbase = (unsigned)__cvta_generic_to_shared(sm);
    const float* Ebi = E + (size_t)row * LSEQ * DPAIR;

    {
        const float4* esrc = (const float4*)Ebi;
        #pragma unroll
        for (int it = 0; it < 8; it++) {
            int g = it*256 + tid;
            int j = g >> 5, d = (g & 31) * 4;
            cp_async16(sbase + (unsigned)((BK_E0 + j*ROWF + d) * 4), esrc + g);
        }
        asm volatile("cp.async.commit_group;");
    }

    for (int k = tid; k < DPAIR*NH; k += 256) Wpb_s[k] = Wpb[k];

    float* gb = g_bias + (size_t)row * NH * LSEQ;

    for (int jt = 0; jt < LSEQ/TJ; jt++) {
        float* e_s = sm + ((jt & 1) ? BK_E1 : BK_E0);

        if (jt + 1 < LSEQ/TJ) {
            const float4* nsrc = (const float4*)(Ebi + (size_t)(jt+1)*TJ*DPAIR);
            unsigned bofs = (jt & 1) ? BK_E0 : BK_E1;
            #pragma unroll
            for (int it = 0; it < 8; it++) {
                int g = it*256 + tid;
                int j = g >> 5, d = (g & 31) * 4;
                cp_async16(sbase + (unsigned)((bofs + j*ROWF + d) * 4), nsrc + g);
            }
            asm volatile("cp.async.commit_group;");
            asm volatile("cp.async.wait_group 1;");
        } else {
            asm volatile("cp.async.wait_group 0;");
        }
        __syncthreads();

        int j0 = jt * TJ;

        // phase A: partial dot over 32 dims
        {
            int j = tid & 63, quad = tid >> 6;
            float pb[NH];
            #pragma unroll
            for (int n=0;n<NH;n++) pb[n] = 0.f;
            const float4* er4 = (const float4*)(e_s + j*ROWF + quad*32);
            #pragma unroll
            for (int d4 = 0; d4 < 8; d4++) {
                float4 ev = er4[d4];
                const float* evp = (const float*)&ev;
                #pragma unroll
                for (int r = 0; r < 4; r++) {
                    const float* wrow = Wpb_s + (quad*32 + d4*4 + r)*NH;
                    float4 wA = *(const float4*)(wrow);
                    float4 wB = *(const float4*)(wrow + 4);
                    float e1 = evp[r];
                    pb[0] += e1*wA.x; pb[1] += e1*wA.y;
                    pb[2] += e1*wA.z; pb[3] += e1*wA.w;
                    pb[4] += e1*wB.x; pb[5] += e1*wB.y;
                    pb[6] += e1*wB.z; pb[7] += e1*wB.w;
                }
            }
            float* po = part_s + (quad*64 + j)*9;
            #pragma unroll
            for (int n=0;n<NH;n++) po[n] = pb[n];
        }
        __syncthreads();

        // phase B: reduce 4 quads, write bias to global
        {
            int j = tid & 63, nb = tid >> 6;
            #pragma unroll
            for (int h = 0; h < 2; h++) {
                int n = nb + h*4;
                float bias = part_s[(0*64+j)*9+n] + part_s[(1*64+j)*9+n]
                           + part_s[(2*64+j)*9+n] + part_s[(3*64+j)*9+n];
                gb[n*LSEQ + j0 + j] = bias;
            }
        }
    }
}

// -------- kernel 3b: logits + softmax + out_s/out_p (register probs) -----
__global__ void __launch_bounds__(256) ipa_logits(
    const float* __restrict__ R, const float* __restrict__ T,
    const float* __restrict__ gamma)
{
    __shared__ float qs_s[128];
    __shared__ float qp_s[96];
    __shared__ float op_s[96];

    int row = blockIdx.x;
    int b = row >> 9, i = row & 511;
    int tid = threadIdx.x;
    int warp = tid >> 5, lane = tid & 31;

    if (tid < 128) { int n = tid >> 4, d = tid & 15;
        qs_s[tid] = g_qs[((b*NH+n)*LSEQ + i)*DS + d]; }
    if (tid < 96)  { int n = tid/12, pc = tid - n*12;
        qp_s[tid] = g_qp[((b*NH+n)*LSEQ + i)*12 + pc]; }
    __syncthreads();

    int n = warp;
    float gam = gamma[n];
    const float* gb = g_bias + (size_t)row * NH * LSEQ + n*LSEQ;

    // --- 16 logits per lane, straight into registers ---
    float l[16];
    #pragma unroll
    for (int k = 0; k < 16; k++) {
        int j = lane + k*32;
        const float4* kr = (const float4*)(g_ks + ((b*NH+n)*LSEQ + j)*DS);
        float dot = 0.f;
        #pragma unroll
        for (int q4 = 0; q4 < 4; q4++) {
            float4 kv = kr[q4];
            const float* qq = qs_s + n*DS + q4*4;
            dot += qq[0]*kv.x + qq[1]*kv.y + qq[2]*kv.z + qq[3]*kv.w;
        }
        const float4* kp = (const float4*)(g_kp + ((b*NH+n)*LSEQ + j)*12);
        float sq = 0.f;
        #pragma unroll
        for (int q4 = 0; q4 < 3; q4++) {
            float4 kv = kp[q4];
            const float* qq = qp_s + n*12 + q4*4;
            float d0 = qq[0]-kv.x, d1 = qq[1]-kv.y, d2 = qq[2]-kv.z, d3 = qq[3]-kv.w;
            sq += d0*d0 + d1*d1 + d2*d2 + d3*d3;
        }
        l[k] = SCALE_TOTAL*(SCALE_SCALAR*dot + gb[j] - 0.5f*SCALE_POINT*gam*sq);
    }

    // --- softmax in registers (warp = head) ---
    float m = -1e30f;
    #pragma unroll
    for (int k = 0; k < 16; k++) m = fmaxf(m, l[k]);
    #pragma unroll
    for (int o = 16; o > 0; o >>= 1)
        m = fmaxf(m, __shfl_xor_sync(0xffffffffu, m, o));
    float s = 0.f;
    #pragma unroll
    for (int k = 0; k < 16; k++) { l[k] = __expf(l[k] - m); s += l[k]; }
    #pragma unroll
    for (int o = 16; o > 0; o >>= 1)
        s += __shfl_xor_sync(0xffffffffu, s, o);
    float inv = 1.f / s;
    #pragma unroll
    for (int k = 0; k < 16; k++) l[k] *= inv;

    // --- probs -> global (coalesced 128B stores per head row) ---
    {
        float* gp = g_probs + (size_t)row * NH * LSEQ + n*LSEQ;
        #pragma unroll
        for (int k = 0; k < 16; k++) gp[lane + k*32] = l[k];
    }

    // --- out_s / out_p: probs in registers, vector loads, shuffle reduce --
    float4 acc_s0 = {0,0,0,0}, acc_s1 = {0,0,0,0}, acc_s2 = {0,0,0,0}, acc_s3 = {0,0,0,0};
    float4 acc_p0 = {0,0,0,0}, acc_p1 = {0,0,0,0}, acc_p2 = {0,0,0,0};
    #pragma unroll
    for (int k = 0; k < 16; k++) {
        int j = lane + k*32;
        float p = l[k];
        const float4* v4 = (const float4*)(g_vs + ((size_t)(b*NH+n)*LSEQ + j)*DS);
        float4 a0 = v4[0], a1 = v4[1], a2 = v4[2], a3 = v4[3];
        acc_s0.x += p*a0.x; acc_s0.y += p*a0.y; acc_s0.z += p*a0.z; acc_s0.w += p*a0.w;
        acc_s1.x += p*a1.x; acc_s1.y += p*a1.y; acc_s1.z += p*a1.z; acc_s1.w += p*a1.w;
        acc_s2.x += p*a2.x; acc_s2.y += p*a2.y; acc_s2.z += p*a2.z; acc_s2.w += p*a2.w;
        acc_s3.x += p*a3.x; acc_s3.y += p*a3.y; acc_s3.z += p*a3.z; acc_s3.w += p*a3.w;
        const float4* p4 = (const float4*)(g_vp + ((size_t)(b*NH+n)*LSEQ + j)*12);
        float4 b0 = p4[0], b1 = p4[1], b2 = p4[2];
        acc_p0.x += p*b0.x; acc_p0.y += p*b0.y; acc_p0.z += p*b0.z; acc_p0.w += p*b0.w;
        acc_p1.x += p*b1.x; acc_p1.y += p*b1.y; acc_p1.z += p*b1.z; acc_p1.w += p*b1.w;
        acc_p2.x += p*b2.x; acc_p2.y += p*b2.y; acc_p2.z += p*b2.z; acc_p2.w += p*b2.w;
    }
    // butterfly reduce 28 floats across the warp
    float red[28] = {
        acc_s0.x, acc_s0.y, acc_s0.z, acc_s0.w,
        acc_s1.x, acc_s1.y, acc_s1.z, acc_s1.w,
        acc_s2.x, acc_s2.y, acc_s2.z, acc_s2.w,
        acc_s3.x, acc_s3.y, acc_s3.z, acc_s3.w,
        acc_p0.x, acc_p0.y, acc_p0.z, acc_p0.w,
        acc_p1.x, acc_p1.y, acc_p1.z, acc_p1.w,
        acc_p2.x, acc_p2.y, acc_p2.z, acc_p2.w };
    #pragma unroll
    for (int o = 16; o > 0; o >>= 1) {
        #pragma unroll
        for (int c = 0; c < 28; c++)
            red[c] += __shfl_xor_sync(0xffffffffu, red[c], o);
    }

    float* feat = g_feat + (size_t)row * NFEAT;
    if (lane == 0) {
        #pragma unroll
        for (int d = 0; d < 16; d++) feat[n*DS + d] = red[d];
        #pragma unroll
        for (int c = 0; c < 12; c++) op_s[n*12 + c] = red[16 + c];
    }
    __syncthreads();

    if (tid < 32) {
        int nn = tid >> 2, p = tid & 3;
        const float* rr = R + row*9;
        const float* tt = T + row*3;
        float o0 = op_s[nn*12+p*3+0] - tt[0];
        float o1 = op_s[nn*12+p*3+1] - tt[1];
        float o2 = op_s[nn*12+p*3+2] - tt[2];
        float nsq = 0.f;
        #pragma unroll
        for (int c = 0; c < 3; c++) {
            float lc = o0*rr[c*3+0] + o1*rr[c*3+1] + o2*rr[c*3+2];
            feat[1152 + nn*12 + p*3 + c] = lc;
            nsq += lc*lc;
        }
        feat[1248 + nn*4 + p] = sqrtf(nsq);
    }
}

// ------ kernel 3c: out_pair = P @ E (streaming, probs in smem) -----------
#define K2_E0     0
#define K2_E1     8448
#define K2_P      16896          /* [n][512] = 4096 */
#define K2_FLOATS 20992

__global__ void __launch_bounds__(256) ipa_pair(const float* __restrict__ E)
{
    extern __shared__ float sm[];
    float* p_s = sm + K2_P;

    int row = blockIdx.x;
    int tid = threadIdx.x;
    int jl = tid >> 5, dl = tid & 31;

    unsigned sbase = (unsigned)__cvta_generic_to_shared(sm);
    const float* Ebi = E + (size_t)row * LSEQ * DPAIR;

    {
        const float4* esrc = (const float4*)Ebi;
        #pragma unroll
        for (int it = 0; it < 8; it++) {
            int g = it*256 + tid;
            int j = g >> 5, d = (g & 31) * 4;
            cp_async16(sbase + (unsigned)((K2_E0 + j*ROWF + d) * 4), esrc + g);
        }
        asm volatile("cp.async.commit_group;");
    }

    {
        const float4* gp4 = (const float4*)(g_probs + (size_t)row * NH * LSEQ);
        #pragma unroll
        for (int k = 0; k < 4; k++) {
            int o = tid + k*256;
            *(float4*)&p_s[o*4] = gp4[o];
        }
    }

    float acc[NH][4];
    #pragma unroll
    for (int n=0;n<NH;n++)
        #pragma unroll
        for (int c=0;c<4;c++) acc[n][c] = 0.f;

    for (int jt = 0; jt < LSEQ/TJ; jt++) {
        float* e_s = sm + ((jt & 1) ? K2_E1 : K2_E0);

        if (jt + 1 < LSEQ/TJ) {
            const float4* nsrc = (const float4*)(Ebi + (size_t)(jt+1)*TJ*DPAIR);
            unsigned bofs = (jt & 1) ? K2_E0 : K2_E1;
            #pragma unroll
            for (int it = 0; it < 8; it++) {
                int g = it*256 + tid;
                int j = g >> 5, d = (g & 31) * 4;
                cp_async16(sbase + (unsigned)((bofs + j*ROWF + d) * 4), nsrc + g);
            }
            asm volatile("cp.async.commit_group;");
            asm volatile("cp.async.wait_group 1;");
        } else {
            asm volatile("cp.async.wait_group 0;");
        }
        __syncthreads();

        int j0 = jt * TJ;
        #pragma unroll
        for (int jj = 0; jj < 8; jj++) {
            int j = jl*8 + jj;
            float4 ev = *(const float4*)(e_s + j*ROWF + dl*4);
            const float* pj = p_s + j0 + j;
            #pragma unroll
            for (int n=0;n<NH;n++) {
                float p = pj[n*LSEQ];
                acc[n][0] += p*ev.x; acc[n][1] += p*ev.y;
                acc[n][2] += p*ev.z; acc[n][3] += p*ev.w;
            }
        }
        __syncthreads();
    }

    float* red = sm + K2_E0;
    #pragma unroll
    for (int n=0;n<NH;n++)
        *(float4*)(red + (jl*NH + n)*128 + dl*4) =
            make_float4(acc[n][0], acc[n][1], acc[n][2], acc[n][3]);
    __syncthreads();

    float* feat = g_feat + (size_t)row * NFEAT + 128;
    #pragma unroll
    for (int k = 0; k < 4; k++) {
        int o = tid + k*256;
        int n = o >> 7, d = o & 127;
        float s = 0.f;
        #pragma unroll
        for (int w = 0; w < 8; w++) s += red[(w*NH+n)*128 + d];
        feat[n*128 + d] = s;
    }
}

// ------------- kernel 4: output GEMM, 4-way split-K partials --------------
__global__ void __launch_bounds__(64) out_gemm_sk(const float* __restrict__ Wout)
{
    __shared__ float As[2][16*36];
    __shared__ float Bs[2][16*32];
    const int tid = threadIdx.x;
    const int tx = tid & 7, ty = tid >> 3;
    const int row0 = blockIdx.y * 32;
    const int col0 = blockIdx.x * 32;
    const int kbase = blockIdx.z * KSPLIT;

    const int a_m0 = tid >> 2, a_k4 = tid & 3;
    const int b_k0 = tid >> 3, b_n4 = tid & 7;

    ull acc2[4][2];
    #pragma unroll
    for (int i=0;i<4;i++) { acc2[i][0]=0ull; acc2[i][1]=0ull; }

    {
        #pragma unroll
        for (int s=0;s<2;s++) {
            int m = a_m0 + s*16;
            float4 v = *(const float4*)&g_feat[(size_t)(row0+m)*NFEAT + kbase + a_k4*4];
            #pragma unroll
            for (int u=0;u<4;u++) As[0][(a_k4*4+u)*36 + m] = ((const float*)&v)[u];
            int k = b_k0 + s*8;
            *(float4*)&Bs[0][k*32 + b_n4*4] =
                *(const float4*)&Wout[(size_t)k*DRES + kbase*0 + (size_t)(kbase+k)*0 + col0 + b_n4*4];
        }
        // fix: B prologue must read from kbase
        #pragma unroll
        for (int s=0;s<2;s++) {
            int k = b_k0 + s*8;
            *(float4*)&Bs[0][k*32 + b_n4*4] =
                *(const float4*)&Wout[(size_t)(kbase+k)*DRES + col0 + b_n4*4];
        }
    }
    __syncthreads();

    const int KB = KSPLIT/16;
    for (int kb = 0; kb < KB; kb++) {
        int cur = kb & 1;
        float4 va[2], vb[2];
        bool has = (kb+1 < KB);
        if (has) {
            int k0 = kbase + (kb+1)*16;
            #pragma unroll
            for (int s=0;s<2;s++) {
                int m = a_m0 + s*16;
                va[s] = *(const float4*)&g_feat[(size_t)(row0+m)*NFEAT + k0 + a_k4*4];
                int k = b_k0 + s*8;
                vb[s] = *(const float4*)&Wout[(size_t)(k0+k)*DRES + col0 + b_n4*4];
            }
        }
        #pragma unroll
        for (int kk = 0; kk < 16; kk++) {
            float4 a = *(const float4*)&As[cur][kk*36 + ty*4];
            float4 b = *(const float4*)&Bs[cur][kk*32 + tx*4];
            ull b01 = pk2(b.x, b.y), b23 = pk2(b.z, b.w);
            const float* ap = (const float*)&a;
            #pragma unroll
            for (int i=0;i<4;i++) {
                ull aa = pk2(ap[i], ap[i]);
                acc2[i][0] = ffma2(aa, b01, acc2[i][0]);
                acc2[i][1] = ffma2(aa, b23, acc2[i][1]);
            }
        }
        if (has) {
            int nxt = cur ^ 1;
            #pragma unroll
            for (int s=0;s<2;s++) {
                int m = a_m0 + s*16;
                #pragma unroll
                for (int u=0;u<4;u++) As[nxt][(a_k4*4+u)*36 + m] = ((const float*)&va[s])[u];
                int k = b_k0 + s*8;
                *(float4*)&Bs[nxt][k*32 + b_n4*4] = vb[s];
            }
        }
        __syncthreads();
    }

    float* dst = g_opart + (size_t)blockIdx.z * NROW * DRES;
    #pragma unroll
    for (int i=0;i<4;i++) {
        int row = row0 + ty*4 + i;
        float2 u0 = up2(acc2[i][0]), u1 = up2(acc2[i][1]);
        float4 o; o.x = u0.x; o.y = u0.y; o.z = u1.x; o.w = u1.y;
        *(float4*)&dst[(size_t)row*DRES + col0 + tx*4] = o;
    }
}

__global__ void __launch_bounds__(256) out_reduce(
    const float* __restrict__ bout, float* __restrict__ out)
{
    const int STRIDE4 = NROW*DRES/4;
    int i4 = blockIdx.x * 256 + threadIdx.x;
    const float4* p = (const float4*)g_opart;
    float4 a = p[i4], b = p[STRIDE4 + i4], c = p[2*STRIDE4 + i4], d = p[3*STRIDE4 + i4];
    int col = (i4 * 4) % DRES;
    float4 bb = *(const float4*)&bout[col];
    float4 o;
    o.x = a.x + b.x + c.x + d.x + bb.x;
    o.y = a.y + b.y + c.y + d.y + bb.y;
    o.z = a.z + b.z + c.z + d.z + bb.z;
    o.w = a.w + b.w + c.w + d.w + bb.w;
    ((float4*)out)[i4] = o;
}

// ---------------- launch ----------------
extern "C" void kernel_launch(void* const* d_in, const int* in_sizes, int n_in,
                              void* d_out, int out_size)
{
    const float* x     = (const float*)d_in[0];
    const float* e     = (const float*)d_in[1];
    const float* r     = (const float*)d_in[2];
    const float* t     = (const float*)d_in[3];
    const float* Wqs   = (const float*)d_in[4];
    const float* Wks   = (const float*)d_in[5];
    const float* Wvs   = (const float*)d_in[6];
    const float* Wpb   = (const float*)d_in[7];
    const float* Wqp   = (const float*)d_in[8];
    const float* Wkp   = (const float*)d_in[9];
    const float* Wvp   = (const float*)d_in[10];
    const float* gamma = (const float*)d_in[11];
    const float* Wout  = (const float*)d_in[12];
    const float* bout  = (const float*)d_in[13];
    float* out = (float*)d_out;

    proj_gemm<<<dim3(21, 32), 64>>>(x, Wqs, Wks, Wvs, Wqp, Wkp, Wvp);
    point_transform<<<NROW, 96>>>(r, t);

    cudaFuncSetAttribute(ipa_bias, cudaFuncAttributeMaxDynamicSharedMemorySize,
                         BK_FLOATS * (int)sizeof(float));
    ipa_bias<<<NROW, 256, BK_FLOATS * sizeof(float)>>>(e, Wpb);

    ipa_logits<<<NROW, 256>>>(r, t, gamma);

    cudaFuncSetAttribute(ipa_pair, cudaFuncAttributeMaxDynamicSharedMemorySize,
                         K2_FLOATS * (int)sizeof(float));
    ipa_pair<<<NROW, 256, K2_FLOATS * sizeof(float)>>>(e);

    out_gemm_sk<<<dim3(12, 32, NSPLIT), 64>>>(Wout);
    out_reduce<<<NROW*DRES/4/256, 256>>>(bout, out);
}

// round 15
// speedup vs baseline: 1.2728x; 1.0392x over previous
#include <cuda_runtime.h>
#include <math.h>

#define NH      8
#define LSEQ    512
#define DRES    384
#define DPAIR   128
#define DS      16
#define TJ      64
#define ROWF    132
#define NROW    1024
#define NFEAT   1280
#define NSPLIT  4
#define KSPLIT  (NFEAT/NSPLIT)

#define SCALE_SCALAR 0.25f
#define SCALE_POINT  0.2357022603955158f   /* 18^-0.5 */
#define SCALE_TOTAL  0.5773502691896258f   /* 3^-0.5  */

typedef unsigned long long ull;

__device__ __forceinline__ ull pk2(float x, float y) {
    ull r; asm("mov.b64 %0,{%1,%2};" : "=l"(r) : "f"(x), "f"(y)); return r;
}
__device__ __forceinline__ ull ffma2(ull a, ull b, ull c) {
    ull d; asm("fma.rn.f32x2 %0,%1,%2,%3;" : "=l"(d) : "l"(a), "l"(b), "l"(c)); return d;
}
__device__ __forceinline__ float2 up2(ull v) {
    float2 r; asm("mov.b64 {%0,%1},%2;" : "=f"(r.x), "=f"(r.y) : "l"(v)); return r;
}
__device__ __forceinline__ void cp_async16(unsigned smem_addr, const void* gptr) {
    asm volatile("cp.async.cg.shared.global [%0], [%1], 16;"
                 :: "r"(smem_addr), "l"(gptr));
}

// ---------------- scratch (device globals; no allocation) ----------------
__device__ float g_qs[2*NH*LSEQ*DS];
__device__ float g_ksT[2*NH*DS*LSEQ];     // [b][n][d][l]  (transposed)
__device__ float g_vsT[2*NH*DS*LSEQ];     // [b][n][d][l]  (transposed)
__device__ float g_qp[2*NH*LSEQ*12];
__device__ float g_kpT[2*NH*12*LSEQ];     // [b][n][pc][l] (transposed)
__device__ float g_vpT[2*NH*12*LSEQ];     // [b][n][pc][l] (transposed)
__device__ float g_praw[NROW*288];
__device__ float g_feat[(size_t)NROW*NFEAT];
__device__ float g_opart[(size_t)NSPLIT*NROW*DRES];
__device__ float g_probs[(size_t)NROW*NH*LSEQ];
__device__ float g_bias[(size_t)NROW*NH*LSEQ];

// ---------------- kernel 1: projection GEMM ------------------------------
__global__ void __launch_bounds__(64) proj_gemm(
    const float* __restrict__ X,
    const float* __restrict__ Wqs, const float* __restrict__ Wks,
    const float* __restrict__ Wvs, const float* __restrict__ Wqp,
    const float* __restrict__ Wkp, const float* __restrict__ Wvp)
{
    __shared__ float As[2][16*36];
    __shared__ float Bs[2][16*32];
    const int tid = threadIdx.x;
    const int tx = tid & 7, ty = tid >> 3;
    const int row0 = blockIdx.y * 32;
    const int col0 = blockIdx.x * 32;

    const float* Wseg; int segw, cl0;
    if (col0 < 384) {
        int sg = col0 >> 7;
        Wseg = (sg==0) ? Wqs : ((sg==1) ? Wks : Wvs);
        segw = 128; cl0 = col0 & 127;
    } else {
        int c2 = col0 - 384; int sg = c2 / 96;
        Wseg = (sg==0) ? Wqp : ((sg==1) ? Wkp : Wvp);
        segw = 96; cl0 = c2 - sg*96;
    }

    const int a_m0 = tid >> 2, a_k4 = tid & 3;
    const int b_k0 = tid >> 3, b_n4 = tid & 7;

    float acc[4][4];
    #pragma unroll
    for (int i=0;i<4;i++)
        #pragma unroll
        for (int j=0;j<4;j++) acc[i][j]=0.f;

    {
        #pragma unroll
        for (int s=0;s<2;s++) {
            int m = a_m0 + s*16;
            float4 v = *(const float4*)&X[(size_t)(row0+m)*DRES + a_k4*4];
            #pragma unroll
            for (int u=0;u<4;u++) As[0][(a_k4*4+u)*36 + m] = ((const float*)&v)[u];
            int k = b_k0 + s*8;
            *(float4*)&Bs[0][k*32 + b_n4*4] =
                *(const float4*)&Wseg[(size_t)k*segw + cl0 + b_n4*4];
        }
    }
    __syncthreads();

    const int KB = DRES/16;
    for (int kb = 0; kb < KB; kb++) {
        int cur = kb & 1;
        float4 va[2], vb[2];
        bool has = (kb+1 < KB);
        if (has) {
            int k0 = (kb+1)*16;
            #pragma unroll
            for (int s=0;s<2;s++) {
                int m = a_m0 + s*16;
                va[s] = *(const float4*)&X[(size_t)(row0+m)*DRES + k0 + a_k4*4];
                int k = b_k0 + s*8;
                vb[s] = *(const float4*)&Wseg[(size_t)(k0+k)*segw + cl0 + b_n4*4];
            }
        }
        #pragma unroll
        for (int kk = 0; kk < 16; kk++) {
            float4 a = *(const float4*)&As[cur][kk*36 + ty*4];
            float4 b = *(const float4*)&Bs[cur][kk*32 + tx*4];
            const float* ap = (const float*)&a;
            const float* bp = (const float*)&b;
            #pragma unroll
            for (int i=0;i<4;i++)
                #pragma unroll
                for (int j=0;j<4;j++) acc[i][j] += ap[i]*bp[j];
        }
        if (has) {
            int nxt = cur ^ 1;
            #pragma unroll
            for (int s=0;s<2;s++) {
                int m = a_m0 + s*16;
                #pragma unroll
                for (int u=0;u<4;u++) As[nxt][(a_k4*4+u)*36 + m] = ((const float*)&va[s])[u];
                int k = b_k0 + s*8;
                *(float4*)&Bs[nxt][k*32 + b_n4*4] = vb[s];
            }
        }
        __syncthreads();
    }

    #pragma unroll
    for (int i=0;i<4;i++) {
        int row = row0 + ty*4 + i;
        int b = row >> 9, l = row & 511;
        #pragma unroll
        for (int j=0;j<4;j++) {
            int col = col0 + tx*4 + j;
            float v = acc[i][j];
            if (col < 384) {
                int sg = col >> 7;
                int n = (col & 127) >> 4, d = col & 15;
                if (sg == 0)
                    g_qs[(((b*NH)+n)*LSEQ + l)*DS + d] = v;
                else if (sg == 1)
                    g_ksT[(((b*NH)+n)*DS + d)*LSEQ + l] = v;
                else
                    g_vsT[(((b*NH)+n)*DS + d)*LSEQ + l] = v;
            } else {
                g_praw[row*288 + (col-384)] = v;
            }
        }
    }
}

// ---------------- kernel 2: euclid transform of projected points ---------
__global__ void point_transform(const float* __restrict__ R, const float* __restrict__ T)
{
    int row = blockIdx.x;
    int b = row >> 9, l = row & 511;
    int t = threadIdx.x;
    if (t >= 96) return;
    int tensor = t / 32, idx = t % 32;
    int n = idx >> 2, p = idx & 3;
    const float* xr = &g_praw[row*288 + tensor*96 + n*12 + p*3];
    const float* rr = &R[row*9];
    const float* tt = &T[row*3];
    float x0 = xr[0], x1 = xr[1], x2 = xr[2];
    float o[3];
    #pragma unroll
    for (int c = 0; c < 3; c++)
        o[c] = x0*rr[0*3+c] + x1*rr[1*3+c] + x2*rr[2*3+c] + tt[c];
    if (tensor == 0) {
        float* dst = g_qp + (((b*NH)+n)*LSEQ + l)*12 + p*3;
        #pragma unroll
        for (int c = 0; c < 3; c++) dst[c] = o[c];
    } else {
        float* base = (tensor==1) ? g_kpT : g_vpT;
        #pragma unroll
        for (int c = 0; c < 3; c++)
            base[(((b*NH)+n)*12 + p*3 + c)*LSEQ + l] = o[c];
    }
}

// -------- kernel 3a: bias = e @ Wpb, streaming (pair-kernel clone) --------
#define BK_E0     0
#define BK_E1     8448
#define BK_WPB    16896
#define BK_PART   17920          /* 256*9 = 2304 */
#define BK_FLOATS 20224

__global__ void __launch_bounds__(256) ipa_bias(
    const float* __restrict__ E, const float* __restrict__ Wpb)
{
    extern __shared__ float sm[];
    float* Wpb_s  = sm + BK_WPB;
    float* part_s = sm + BK_PART;

    int row = blockIdx.x;
    int tid = threadIdx.x;

    unsigned sbase = (unsigned)__cvta_generic_to_shared(sm);
    const float* Ebi = E + (size_t)row * LSEQ * DPAIR;

    {
        const float4* esrc = (const float4*)Ebi;
        #pragma unroll
        for (int it = 0; it < 8; it++) {
            int g = it*256 + tid;
            int j = g >> 5, d = (g & 31) * 4;
            cp_async16(sbase + (unsigned)((BK_E0 + j*ROWF + d) * 4), esrc + g);
        }
        asm volatile("cp.async.commit_group;");
    }

    for (int k = tid; k < DPAIR*NH; k += 256) Wpb_s[k] = Wpb[k];

    float* gb = g_bias + (size_t)row * NH * LSEQ;

    for (int jt = 0; jt < LSEQ/TJ; jt++) {
        float* e_s = sm + ((jt & 1) ? BK_E1 : BK_E0);

        if (jt + 1 < LSEQ/TJ) {
            const float4* nsrc = (const float4*)(Ebi + (size_t)(jt+1)*TJ*DPAIR);
            unsigned bofs = (jt & 1) ? BK_E0 : BK_E1;
            #pragma unroll
            for (int it = 0; it < 8; it++) {
                int g = it*256 + tid;
                int j = g >> 5, d = (g & 31) * 4;
                cp_async16(sbase + (unsigned)((bofs + j*ROWF + d) * 4), nsrc + g);
            }
            asm volatile("cp.async.commit_group;");
            asm volatile("cp.async.wait_group 1;");
        } else {
            asm volatile("cp.async.wait_group 0;");
        }
        __syncthreads();

        int j0 = jt * TJ;

        {
            int j = tid & 63, quad = tid >> 6;
            float pb[NH];
            #pragma unroll
            for (int n=0;n<NH;n++) pb[n] = 0.f;
            const float4* er4 = (const float4*)(e_s + j*ROWF + quad*32);
            #pragma unroll
            for (int d4 = 0; d4 < 8; d4++) {
                float4 ev = er4[d4];
                const float* evp = (const float*)&ev;
                #pragma unroll
                for (int r = 0; r < 4; r++) {
                    const float* wrow = Wpb_s + (quad*32 + d4*4 + r)*NH;
                    float4 wA = *(const float4*)(wrow);
                    float4 wB = *(const float4*)(wrow + 4);
                    float e1 = evp[r];
                    pb[0] += e1*wA.x; pb[1] += e1*wA.y;
                    pb[2] += e1*wA.z; pb[3] += e1*wA.w;
                    pb[4] += e1*wB.x; pb[5] += e1*wB.y;
                    pb[6] += e1*wB.z; pb[7] += e1*wB.w;
                }
            }
            float* po = part_s + (quad*64 + j)*9;
            #pragma unroll
            for (int n=0;n<NH;n++) po[n] = pb[n];
        }
        __syncthreads();

        {
            int j = tid & 63, nb = tid >> 6;
            #pragma unroll
            for (int h = 0; h < 2; h++) {
                int n = nb + h*4;
                float bias = part_s[(0*64+j)*9+n] + part_s[(1*64+j)*9+n]
                           + part_s[(2*64+j)*9+n] + part_s[(3*64+j)*9+n];
                gb[n*LSEQ + j0 + j] = bias;
            }
        }
    }
}

// ---- kernel 3b: logits + softmax + out_s/out_p (coalesced transposed k/v)
__global__ void __launch_bounds__(256) ipa_logits(
    const float* __restrict__ R, const float* __restrict__ T,
    const float* __restrict__ gamma)
{
    __shared__ float qs_s[128];
    __shared__ float qp_s[96];
    __shared__ float op_s[96];

    int row = blockIdx.x;
    int b = row >> 9, i = row & 511;
    int tid = threadIdx.x;
    int warp = tid >> 5, lane = tid & 31;

    if (tid < 128) { int n = tid >> 4, d = tid & 15;
        qs_s[tid] = g_qs[((b*NH+n)*LSEQ + i)*DS + d]; }
    if (tid < 96)  { int n = tid/12, pc = tid - n*12;
        qp_s[tid] = g_qp[((b*NH+n)*LSEQ + i)*12 + pc]; }
    __syncthreads();

    int n = warp;
    float gam = gamma[n];
    const float* gb  = g_bias + (size_t)row * NH * LSEQ + n*LSEQ;
    const float* ksT = g_ksT + (size_t)(b*NH+n)*DS*LSEQ;
    const float* kpT = g_kpT + (size_t)(b*NH+n)*12*LSEQ;
    const float* vsT = g_vsT + (size_t)(b*NH+n)*DS*LSEQ;
    const float* vpT = g_vpT + (size_t)(b*NH+n)*12*LSEQ;

    // --- qk dot + point dist, coalesced scalar loads (1 wavefront each) ---
    float dot[16], sq[16];
    #pragma unroll
    for (int k = 0; k < 16; k++) { dot[k] = 0.f; sq[k] = 0.f; }
    #pragma unroll
    for (int d = 0; d < DS; d++) {
        float q = qs_s[n*DS + d];
        const float* kr = ksT + d*LSEQ + lane;
        #pragma unroll
        for (int k = 0; k < 16; k++) dot[k] += q * kr[k*32];
    }
    #pragma unroll
    for (int pc = 0; pc < 12; pc++) {
        float q = qp_s[n*12 + pc];
        const float* kp = kpT + pc*LSEQ + lane;
        #pragma unroll
        for (int k = 0; k < 16; k++) {
            float dl = q - kp[k*32];
            sq[k] += dl*dl;
        }
    }
    float l[16];
    #pragma unroll
    for (int k = 0; k < 16; k++)
        l[k] = SCALE_TOTAL*(SCALE_SCALAR*dot[k] + gb[lane + k*32]
               - 0.5f*SCALE_POINT*gam*sq[k]);

    // --- softmax in registers (warp = head) ---
    float m = -1e30f;
    #pragma unroll
    for (int k = 0; k < 16; k++) m = fmaxf(m, l[k]);
    #pragma unroll
    for (int o = 16; o > 0; o >>= 1)
        m = fmaxf(m, __shfl_xor_sync(0xffffffffu, m, o));
    float s = 0.f;
    #pragma unroll
    for (int k = 0; k < 16; k++) { l[k] = __expf(l[k] - m); s += l[k]; }
    #pragma unroll
    for (int o = 16; o > 0; o >>= 1)
        s += __shfl_xor_sync(0xffffffffu, s, o);
    float inv = 1.f / s;
    #pragma unroll
    for (int k = 0; k < 16; k++) l[k] *= inv;

    // --- probs -> global (coalesced) ---
    {
        float* gp = g_probs + (size_t)row * NH * LSEQ + n*LSEQ;
        #pragma unroll
        for (int k = 0; k < 16; k++) gp[lane + k*32] = l[k];
    }

    // --- out_s: one dim at a time, coalesced loads, shuffle reduce ---
    float* feat = g_feat + (size_t)row * NFEAT;
    #pragma unroll
    for (int d = 0; d < DS; d++) {
        const float* vr = vsT + d*LSEQ + lane;
        float a = 0.f;
        #pragma unroll
        for (int k = 0; k < 16; k++) a += l[k] * vr[k*32];
        #pragma unroll
        for (int o = 16; o > 0; o >>= 1)
            a += __shfl_xor_sync(0xffffffffu, a, o);
        if (lane == 0) feat[n*DS + d] = a;
    }
    // --- out_p likewise ---
    #pragma unroll
    for (int pc = 0; pc < 12; pc++) {
        const float* vr = vpT + pc*LSEQ + lane;
        float a = 0.f;
        #pragma unroll
        for (int k = 0; k < 16; k++) a += l[k] * vr[k*32];
        #pragma unroll
        for (int o = 16; o > 0; o >>= 1)
            a += __shfl_xor_sync(0xffffffffu, a, o);
        if (lane == 0) op_s[n*12 + pc] = a;
    }
    __syncthreads();

    if (tid < 32) {
        int nn = tid >> 2, p = tid & 3;
        const float* rr = R + row*9;
        const float* tt = T + row*3;
        float o0 = op_s[nn*12+p*3+0] - tt[0];
        float o1 = op_s[nn*12+p*3+1] - tt[1];
        float o2 = op_s[nn*12+p*3+2] - tt[2];
        float nsq = 0.f;
        #pragma unroll
        for (int c = 0; c < 3; c++) {
            float lc = o0*rr[c*3+0] + o1*rr[c*3+1] + o2*rr[c*3+2];
            feat[1152 + nn*12 + p*3 + c] = lc;
            nsq += lc*lc;
        }
        feat[1248 + nn*4 + p] = sqrtf(nsq);
    }
}

// ------ kernel 3c: out_pair = P @ E (streaming, probs in smem) -----------
#define K2_E0     0
#define K2_E1     8448
#define K2_P      16896          /* [n][512] = 4096 */
#define K2_FLOATS 20992

__global__ void __launch_bounds__(256) ipa_pair(const float* __restrict__ E)
{
    extern __shared__ float sm[];
    float* p_s = sm + K2_P;

    int row = blockIdx.x;
    int tid = threadIdx.x;
    int jl = tid >> 5, dl = tid & 31;

    unsigned sbase = (unsigned)__cvta_generic_to_shared(sm);
    const float* Ebi = E + (size_t)row * LSEQ * DPAIR;

    {
        const float4* esrc = (const float4*)Ebi;
        #pragma unroll
        for (int it = 0; it < 8; it++) {
            int g = it*256 + tid;
            int j = g >> 5, d = (g & 31) * 4;
            cp_async16(sbase + (unsigned)((K2_E0 + j*ROWF + d) * 4), esrc + g);
        }
        asm volatile("cp.async.commit_group;");
    }

    {
        const float4* gp4 = (const float4*)(g_probs + (size_t)row * NH * LSEQ);
        #pragma unroll
        for (int k = 0; k < 4; k++) {
            int o = tid + k*256;
            *(float4*)&p_s[o*4] = gp4[o];
        }
    }

    float acc[NH][4];
    #pragma unroll
    for (int n=0;n<NH;n++)
        #pragma unroll
        for (int c=0;c<4;c++) acc[n][c] = 0.f;

    for (int jt = 0; jt < LSEQ/TJ; jt++) {
        float* e_s = sm + ((jt & 1) ? K2_E1 : K2_E0);

        if (jt + 1 < LSEQ/TJ) {
            const float4* nsrc = (const float4*)(Ebi + (size_t)(jt+1)*TJ*DPAIR);
            unsigned bofs = (jt & 1) ? K2_E0 : K2_E1;
            #pragma unroll
            for (int it = 0; it < 8; it++) {
                int g = it*256 + tid;
                int j = g >> 5, d = (g & 31) * 4;
                cp_async16(sbase + (unsigned)((bofs + j*ROWF + d) * 4), nsrc + g);
            }
            asm volatile("cp.async.commit_group;");
            asm volatile("cp.async.wait_group 1;");
        } else {
            asm volatile("cp.async.wait_group 0;");
        }
        __syncthreads();

        int j0 = jt * TJ;
        #pragma unroll
        for (int jj = 0; jj < 8; jj++) {
            int j = jl*8 + jj;
            float4 ev = *(const float4*)(e_s + j*ROWF + dl*4);
            const float* pj = p_s + j0 + j;
            #pragma unroll
            for (int n=0;n<NH;n++) {
                float p = pj[n*LSEQ];
                acc[n][0] += p*ev.x; acc[n][1] += p*ev.y;
                acc[n][2] += p*ev.z; acc[n][3] += p*ev.w;
            }
        }
        __syncthreads();
    }

    float* red = sm + K2_E0;
    #pragma unroll
    for (int n=0;n<NH;n++)
        *(float4*)(red + (jl*NH + n)*128 + dl*4) =
            make_float4(acc[n][0], acc[n][1], acc[n][2], acc[n][3]);
    __syncthreads();

    float* feat = g_feat + (size_t)row * NFEAT + 128;
    #pragma unroll
    for (int k = 0; k < 4; k++) {
        int o = tid + k*256;
        int n = o >> 7, d = o & 127;
        float s = 0.f;
        #pragma unroll
        for (int w = 0; w < 8; w++) s += red[(w*NH+n)*128 + d];
        feat[n*128 + d] = s;
    }
}

// ------------- kernel 4: output GEMM, 4-way split-K partials --------------
__global__ void __launch_bounds__(64) out_gemm_sk(const float* __restrict__ Wout)
{
    __shared__ float As[2][16*36];
    __shared__ float Bs[2][16*32];
    const int tid = threadIdx.x;
    const int tx = tid & 7, ty = tid >> 3;
    const int row0 = blockIdx.y * 32;
    const int col0 = blockIdx.x * 32;
    const int kbase = blockIdx.z * KSPLIT;

    const int a_m0 = tid >> 2, a_k4 = tid & 3;
    const int b_k0 = tid >> 3, b_n4 = tid & 7;

    ull acc2[4][2];
    #pragma unroll
    for (int i=0;i<4;i++) { acc2[i][0]=0ull; acc2[i][1]=0ull; }

    {
        #pragma unroll
        for (int s=0;s<2;s++) {
            int m = a_m0 + s*16;
            float4 v = *(const float4*)&g_feat[(size_t)(row0+m)*NFEAT + kbase + a_k4*4];
            #pragma unroll
            for (int u=0;u<4;u++) As[0][(a_k4*4+u)*36 + m] = ((const float*)&v)[u];
            int k = b_k0 + s*8;
            *(float4*)&Bs[0][k*32 + b_n4*4] =
                *(const float4*)&Wout[(size_t)(kbase+k)*DRES + col0 + b_n4*4];
        }
    }
    __syncthreads();

    const int KB = KSPLIT/16;
    for (int kb = 0; kb < KB; kb++) {
        int cur = kb & 1;
        float4 va[2], vb[2];
        bool has = (kb+1 < KB);
        if (has) {
            int k0 = kbase + (kb+1)*16;
            #pragma unroll
            for (int s=0;s<2;s++) {
                int m = a_m0 + s*16;
                va[s] = *(const float4*)&g_feat[(size_t)(row0+m)*NFEAT + k0 + a_k4*4];
                int k = b_k0 + s*8;
                vb[s] = *(const float4*)&Wout[(size_t)(k0+k)*DRES + col0 + b_n4*4];
            }
        }
        #pragma unroll
        for (int kk = 0; kk < 16; kk++) {
            float4 a = *(const float4*)&As[cur][kk*36 + ty*4];
            float4 b = *(const float4*)&Bs[cur][kk*32 + tx*4];
            ull b01 = pk2(b.x, b.y), b23 = pk2(b.z, b.w);
            const float* ap = (const float*)&a;
            #pragma unroll
            for (int i=0;i<4;i++) {
                ull aa = pk2(ap[i], ap[i]);
                acc2[i][0] = ffma2(aa, b01, acc2[i][0]);
                acc2[i][1] = ffma2(aa, b23, acc2[i][1]);
            }
        }
        if (has) {
            int nxt = cur ^ 1;
            #pragma unroll
            for (int s=0;s<2;s++) {
                int m = a_m0 + s*16;
                #pragma unroll
                for (int u=0;u<4;u++) As[nxt][(a_k4*4+u)*36 + m] = ((const float*)&va[s])[u];
                int k = b_k0 + s*8;
                *(float4*)&Bs[nxt][k*32 + b_n4*4] = vb[s];
            }
        }
        __syncthreads();
    }

    float* dst = g_opart + (size_t)blockIdx.z * NROW * DRES;
    #pragma unroll
    for (int i=0;i<4;i++) {
        int row = row0 + ty*4 + i;
        float2 u0 = up2(acc2[i][0]), u1 = up2(acc2[i][1]);
        float4 o; o.x = u0.x; o.y = u0.y; o.z = u1.x; o.w = u1.y;
        *(float4*)&dst[(size_t)row*DRES + col0 + tx*4] = o;
    }
}

__global__ void __launch_bounds__(256) out_reduce(
    const float* __restrict__ bout, float* __restrict__ out)
{
    const int STRIDE4 = NROW*DRES/4;
    int i4 = blockIdx.x * 256 + threadIdx.x;
    const float4* p = (const float4*)g_opart;
    float4 a = p[i4], b = p[STRIDE4 + i4], c = p[2*STRIDE4 + i4], d = p[3*STRIDE4 + i4];
    int col = (i4 * 4) % DRES;
    float4 bb = *(const float4*)&bout[col];
    float4 o;
    o.x = a.x + b.x + c.x + d.x + bb.x;
    o.y = a.y + b.y + c.y + d.y + bb.y;
    o.z = a.z + b.z + c.z + d.z + bb.z;
    o.w = a.w + b.w + c.w + d.w + bb.w;
    ((float4*)out)[i4] = o;
}

// ---------------- launch ----------------
extern "C" void kernel_launch(void* const* d_in, const int* in_sizes, int n_in,
                              void* d_out, int out_size)
{
    const float* x     = (const float*)d_in[0];
    const float* e     = (const float*)d_in[1];
    const float* r     = (const float*)d_in[2];
    const float* t     = (const float*)d_in[3];
    const float* Wqs   = (const float*)d_in[4];
    const float* Wks   = (const float*)d_in[5];
    const float* Wvs   = (const float*)d_in[6];
    const float* Wpb   = (const float*)d_in[7];
    const float* Wqp   = (const float*)d_in[8];
    const float* Wkp   = (const float*)d_in[9];
    const float* Wvp   = (const float*)d_in[10];
    const float* gamma = (const float*)d_in[11];
    const float* Wout  = (const float*)d_in[12];
    const float* bout  = (const float*)d_in[13];
    float* out = (float*)d_out;

    proj_gemm<<<dim3(21, 32), 64>>>(x, Wqs, Wks, Wvs, Wqp, Wkp, Wvp);
    point_transform<<<NROW, 96>>>(r, t);

    cudaFuncSetAttribute(ipa_bias, cudaFuncAttributeMaxDynamicSharedMemorySize,
                         BK_FLOATS * (int)sizeof(float));
    ipa_bias<<<NROW, 256, BK_FLOATS * sizeof(float)>>>(e, Wpb);

    ipa_logits<<<NROW, 256>>>(r, t, gamma);

    cudaFuncSetAttribute(ipa_pair, cudaFuncAttributeMaxDynamicSharedMemorySize,
                         K2_FLOATS * (int)sizeof(float));
    ipa_pair<<<NROW, 256, K2_FLOATS * sizeof(float)>>>(e);

    out_gemm_sk<<<dim3(12, 32, NSPLIT), 64>>>(Wout);
    out_reduce<<<NROW*DRES/4/256, 256>>>(bout, out);
}

// round 16
// speedup vs baseline: 1.4156x; 1.1121x over previous
#include <cuda_runtime.h>
#include <math.h>

#define NH      8
#define LSEQ    512
#define DRES    384
#define DPAIR   128
#define DS      16
#define TJ      64
#define ROWF    132
#define NROW    1024
#define NFEAT   1280
#define NSPLIT  4
#define KSPLIT  (NFEAT/NSPLIT)

#define SCALE_SCALAR 0.25f
#define SCALE_POINT  0.2357022603955158f   /* 18^-0.5 */
#define SCALE_TOTAL  0.5773502691896258f   /* 3^-0.5  */

typedef unsigned long long ull;

__device__ __forceinline__ ull pk2(float x, float y) {
    ull r; asm("mov.b64 %0,{%1,%2};" : "=l"(r) : "f"(x), "f"(y)); return r;
}
__device__ __forceinline__ ull ffma2(ull a, ull b, ull c) {
    ull d; asm("fma.rn.f32x2 %0,%1,%2,%3;" : "=l"(d) : "l"(a), "l"(b), "l"(c)); return d;
}
__device__ __forceinline__ float2 up2(ull v) {
    float2 r; asm("mov.b64 {%0,%1},%2;" : "=f"(r.x), "=f"(r.y) : "l"(v)); return r;
}
__device__ __forceinline__ void cp_async16(unsigned smem_addr, const void* gptr) {
    asm volatile("cp.async.cg.shared.global [%0], [%1], 16;"
                 :: "r"(smem_addr), "l"(gptr));
}

// ---------------- scratch (device globals; no allocation) ----------------
__device__ float g_qs[2*NH*LSEQ*DS];
__device__ float g_ksT[2*NH*DS*LSEQ];     // [b][n][d][l]
__device__ float g_vsT[2*NH*DS*LSEQ];     // [b][n][d][l]
__device__ float g_qp[2*NH*LSEQ*12];
__device__ float g_kpT[2*NH*12*LSEQ];     // [b][n][pc][l]
__device__ float g_vpT[2*NH*12*LSEQ];     // [b][n][pc][l]
__device__ float g_kk2[2*NH*LSEQ];        // sum over p,c of kp^2
__device__ float g_praw[NROW*288];
__device__ float g_feat[(size_t)NROW*NFEAT];
__device__ float g_opart[(size_t)NSPLIT*NROW*DRES];
__device__ float g_probs[(size_t)NROW*NH*LSEQ];
__device__ float g_bias[(size_t)NROW*NH*LSEQ];

// ---------------- kernel 1: projection GEMM ------------------------------
__global__ void __launch_bounds__(64) proj_gemm(
    const float* __restrict__ X,
    const float* __restrict__ Wqs, const float* __restrict__ Wks,
    const float* __restrict__ Wvs, const float* __restrict__ Wqp,
    const float* __restrict__ Wkp, const float* __restrict__ Wvp)
{
    __shared__ float As[2][16*36];
    __shared__ float Bs[2][16*32];
    const int tid = threadIdx.x;
    const int tx = tid & 7, ty = tid >> 3;
    const int row0 = blockIdx.y * 32;
    const int col0 = blockIdx.x * 32;

    const float* Wseg; int segw, cl0;
    if (col0 < 384) {
        int sg = col0 >> 7;
        Wseg = (sg==0) ? Wqs : ((sg==1) ? Wks : Wvs);
        segw = 128; cl0 = col0 & 127;
    } else {
        int c2 = col0 - 384; int sg = c2 / 96;
        Wseg = (sg==0) ? Wqp : ((sg==1) ? Wkp : Wvp);
        segw = 96; cl0 = c2 - sg*96;
    }

    const int a_m0 = tid >> 2, a_k4 = tid & 3;
    const int b_k0 = tid >> 3, b_n4 = tid & 7;

    float acc[4][4];
    #pragma unroll
    for (int i=0;i<4;i++)
        #pragma unroll
        for (int j=0;j<4;j++) acc[i][j]=0.f;

    {
        #pragma unroll
        for (int s=0;s<2;s++) {
            int m = a_m0 + s*16;
            float4 v = *(const float4*)&X[(size_t)(row0+m)*DRES + a_k4*4];
            #pragma unroll
            for (int u=0;u<4;u++) As[0][(a_k4*4+u)*36 + m] = ((const float*)&v)[u];
            int k = b_k0 + s*8;
            *(float4*)&Bs[0][k*32 + b_n4*4] =
                *(const float4*)&Wseg[(size_t)k*segw + cl0 + b_n4*4];
        }
    }
    __syncthreads();

    const int KB = DRES/16;
    for (int kb = 0; kb < KB; kb++) {
        int cur = kb & 1;
        float4 va[2], vb[2];
        bool has = (kb+1 < KB);
        if (has) {
            int k0 = (kb+1)*16;
            #pragma unroll
            for (int s=0;s<2;s++) {
                int m = a_m0 + s*16;
                va[s] = *(const float4*)&X[(size_t)(row0+m)*DRES + k0 + a_k4*4];
                int k = b_k0 + s*8;
                vb[s] = *(const float4*)&Wseg[(size_t)(k0+k)*segw + cl0 + b_n4*4];
            }
        }
        #pragma unroll
        for (int kk = 0; kk < 16; kk++) {
            float4 a = *(const float4*)&As[cur][kk*36 + ty*4];
            float4 b = *(const float4*)&Bs[cur][kk*32 + tx*4];
            const float* ap = (const float*)&a;
            const float* bp = (const float*)&b;
            #pragma unroll
            for (int i=0;i<4;i++)
                #pragma unroll
                for (int j=0;j<4;j++) acc[i][j] += ap[i]*bp[j];
        }
        if (has) {
            int nxt = cur ^ 1;
            #pragma unroll
            for (int s=0;s<2;s++) {
                int m = a_m0 + s*16;
                #pragma unroll
                for (int u=0;u<4;u++) As[nxt][(a_k4*4+u)*36 + m] = ((const float*)&va[s])[u];
                int k = b_k0 + s*8;
                *(float4*)&Bs[nxt][k*32 + b_n4*4] = vb[s];
            }
        }
        __syncthreads();
    }

    #pragma unroll
    for (int i=0;i<4;i++) {
        int row = row0 + ty*4 + i;
        int b = row >> 9, l = row & 511;
        #pragma unroll
        for (int j=0;j<4;j++) {
            int col = col0 + tx*4 + j;
            float v = acc[i][j];
            if (col < 384) {
                int sg = col >> 7;
                int n = (col & 127) >> 4, d = col & 15;
                if (sg == 0)
                    g_qs[(((b*NH)+n)*LSEQ + l)*DS + d] = v;
                else if (sg == 1)
                    g_ksT[(((b*NH)+n)*DS + d)*LSEQ + l] = v;
                else
                    g_vsT[(((b*NH)+n)*DS + d)*LSEQ + l] = v;
            } else {
                g_praw[row*288 + (col-384)] = v;
            }
        }
    }
}

// ------ kernel 2: euclid transform of projected points + kk2 -------------
__global__ void point_transform(const float* __restrict__ R, const float* __restrict__ T)
{
    __shared__ float kkp[32];
    int row = blockIdx.x;
    int b = row >> 9, l = row & 511;
    int t = threadIdx.x;
    if (t < 96) {
        int tensor = t / 32, idx = t % 32;
        int n = idx >> 2, p = idx & 3;
        const float* xr = &g_praw[row*288 + tensor*96 + n*12 + p*3];
        const float* rr = &R[row*9];
        const float* tt = &T[row*3];
        float x0 = xr[0], x1 = xr[1], x2 = xr[2];
        float o[3];
        #pragma unroll
        for (int c = 0; c < 3; c++)
            o[c] = x0*rr[0*3+c] + x1*rr[1*3+c] + x2*rr[2*3+c] + tt[c];
        if (tensor == 0) {
            float* dst = g_qp + (((b*NH)+n)*LSEQ + l)*12 + p*3;
            #pragma unroll
            for (int c = 0; c < 3; c++) dst[c] = o[c];
        } else {
            float* base = (tensor==1) ? g_kpT : g_vpT;
            #pragma unroll
            for (int c = 0; c < 3; c++)
                base[(((b*NH)+n)*12 + p*3 + c)*LSEQ + l] = o[c];
            if (tensor == 1)
                kkp[idx] = o[0]*o[0] + o[1]*o[1] + o[2]*o[2];
        }
    }
    __syncthreads();
    if (t < 8)
        g_kk2[(b*NH + t)*LSEQ + l] = kkp[t*4] + kkp[t*4+1] + kkp[t*4+2] + kkp[t*4+3];
}

// -------- kernel 3a: bias = e @ Wpb, streaming ----------------------------
#define BK_E0     0
#define BK_E1     8448
#define BK_WPB    16896
#define BK_PART   17920
#define BK_FLOATS 20224

__global__ void __launch_bounds__(256) ipa_bias(
    const float* __restrict__ E, const float* __restrict__ Wpb)
{
    extern __shared__ float sm[];
    float* Wpb_s  = sm + BK_WPB;
    float* part_s = sm + BK_PART;

    int row = blockIdx.x;
    int tid = threadIdx.x;

    unsigned sbase = (unsigned)__cvta_generic_to_shared(sm);
    const float* Ebi = E + (size_t)row * LSEQ * DPAIR;

    {
        const float4* esrc = (const float4*)Ebi;
        #pragma unroll
        for (int it = 0; it < 8; it++) {
            int g = it*256 + tid;
            int j = g >> 5, d = (g & 31) * 4;
            cp_async16(sbase + (unsigned)((BK_E0 + j*ROWF + d) * 4), esrc + g);
        }
        asm volatile("cp.async.commit_group;");
    }

    for (int k = tid; k < DPAIR*NH; k += 256) Wpb_s[k] = Wpb[k];

    float* gb = g_bias + (size_t)row * NH * LSEQ;

    for (int jt = 0; jt < LSEQ/TJ; jt++) {
        float* e_s = sm + ((jt & 1) ? BK_E1 : BK_E0);

        if (jt + 1 < LSEQ/TJ) {
            const float4* nsrc = (const float4*)(Ebi + (size_t)(jt+1)*TJ*DPAIR);
            unsigned bofs = (jt & 1) ? BK_E0 : BK_E1;
            #pragma unroll
            for (int it = 0; it < 8; it++) {
                int g = it*256 + tid;
                int j = g >> 5, d = (g & 31) * 4;
                cp_async16(sbase + (unsigned)((bofs + j*ROWF + d) * 4), nsrc + g);
            }
            asm volatile("cp.async.commit_group;");
            asm volatile("cp.async.wait_group 1;");
        } else {
            asm volatile("cp.async.wait_group 0;");
        }
        __syncthreads();

        int j0 = jt * TJ;

        {
            int j = tid & 63, quad = tid >> 6;
            float pb[NH];
            #pragma unroll
            for (int n=0;n<NH;n++) pb[n] = 0.f;
            const float4* er4 = (const float4*)(e_s + j*ROWF + quad*32);
            #pragma unroll
            for (int d4 = 0; d4 < 8; d4++) {
                float4 ev = er4[d4];
                const float* evp = (const float*)&ev;
                #pragma unroll
                for (int r = 0; r < 4; r++) {
                    const float* wrow = Wpb_s + (quad*32 + d4*4 + r)*NH;
                    float4 wA = *(const float4*)(wrow);
                    float4 wB = *(const float4*)(wrow + 4);
                    float e1 = evp[r];
                    pb[0] += e1*wA.x; pb[1] += e1*wA.y;
                    pb[2] += e1*wA.z; pb[3] += e1*wA.w;
                    pb[4] += e1*wB.x; pb[5] += e1*wB.y;
                    pb[6] += e1*wB.z; pb[7] += e1*wB.w;
                }
            }
            float* po = part_s + (quad*64 + j)*9;
            #pragma unroll
            for (int n=0;n<NH;n++) po[n] = pb[n];
        }
        __syncthreads();

        {
            int j = tid & 63, nb = tid >> 6;
            #pragma unroll
            for (int h = 0; h < 2; h++) {
                int n = nb + h*4;
                float bias = part_s[(0*64+j)*9+n] + part_s[(1*64+j)*9+n]
                           + part_s[(2*64+j)*9+n] + part_s[(3*64+j)*9+n];
                gb[n*LSEQ + j0 + j] = bias;
            }
        }
    }
}

// ---- kernel 3b: logits+softmax+out_s/out_p, 2 queries per block ---------
__global__ void __launch_bounds__(256) ipa_logits(
    const float* __restrict__ R, const float* __restrict__ T,
    const float* __restrict__ gamma)
{
    __shared__ float qs_s[2][128];
    __shared__ float qp_s[2][96];
    __shared__ float qq2_s[2][8];
    __shared__ float op_s[2][96];
    __shared__ float gam_s[8];

    int rowb = blockIdx.x * 2;
    int b = rowb >> 9;
    int tid = threadIdx.x;
    int warp = tid >> 5, lane = tid & 31;

    if (tid < 256) {
        int r = tid >> 7, q = tid & 127;        // 2 rows x 128 qs entries
        int n = q >> 4, d = q & 15;
        qs_s[r][q] = g_qs[((b*NH+n)*LSEQ + ((rowb+r) & 511))*DS + d];
    }
    if (tid < 192) {
        int r = tid / 96, q = tid - r*96;
        int n = q/12, pc = q - n*12;
        qp_s[r][q] = g_qp[((b*NH+n)*LSEQ + ((rowb+r) & 511))*12 + pc];
    }
    if (tid < 8) gam_s[tid] = gamma[tid];
    __syncthreads();
    if (tid < 16) {
        int r = tid >> 3, n = tid & 7;
        float s = 0.f;
        #pragma unroll
        for (int pc = 0; pc < 12; pc++) { float v = qp_s[r][n*12+pc]; s += v*v; }
        qq2_s[r][n] = s;
    }
    __syncthreads();

    int n = warp;
    float spg = SCALE_POINT * gam_s[n];
    const float* ksT = g_ksT + (size_t)(b*NH+n)*DS*LSEQ;
    const float* kpT = g_kpT + (size_t)(b*NH+n)*12*LSEQ;
    const float* vsT = g_vsT + (size_t)(b*NH+n)*DS*LSEQ;
    const float* vpT = g_vpT + (size_t)(b*NH+n)*12*LSEQ;
    const float* gb0 = g_bias + (size_t)rowb     * NH * LSEQ + n*LSEQ;
    const float* gb1 = g_bias + (size_t)(rowb+1) * NH * LSEQ + n*LSEQ;

    // --- combined-scale accumulation: acc = SS*qk_dot + SPg*qp_dot ---
    float acc0[16], acc1[16];
    #pragma unroll
    for (int k = 0; k < 16; k++) { acc0[k] = 0.f; acc1[k] = 0.f; }
    #pragma unroll
    for (int d = 0; d < DS; d++) {
        float q0 = SCALE_SCALAR * qs_s[0][n*DS + d];
        float q1 = SCALE_SCALAR * qs_s[1][n*DS + d];
        const float* kr = ksT + d*LSEQ + lane;
        #pragma unroll
        for (int k = 0; k < 16; k++) {
            float kv = kr[k*32];
            acc0[k] += q0*kv; acc1[k] += q1*kv;
        }
    }
    #pragma unroll
    for (int pc = 0; pc < 12; pc++) {
        float q0 = spg * qp_s[0][n*12 + pc];
        float q1 = spg * qp_s[1][n*12 + pc];
        const float* kp = kpT + pc*LSEQ + lane;
        #pragma unroll
        for (int k = 0; k < 16; k++) {
            float kv = kp[k*32];
            acc0[k] += q0*kv; acc1[k] += q1*kv;
        }
    }
    // --- finish logits: + bias - 0.5*SPg*(qq2 + kk2) ---
    {
        float c0 = -0.5f*spg*qq2_s[0][n];
        float c1 = -0.5f*spg*qq2_s[1][n];
        const float* kk = g_kk2 + (size_t)(b*NH+n)*LSEQ + lane;
        #pragma unroll
        for (int k = 0; k < 16; k++) {
            float kkt = -0.5f*spg*kk[k*32];
            acc0[k] = SCALE_TOTAL*(acc0[k] + gb0[lane + k*32] + c0 + kkt);
            acc1[k] = SCALE_TOTAL*(acc1[k] + gb1[lane + k*32] + c1 + kkt);
        }
    }

    // --- softmax per row (warp = head) ---
    #pragma unroll
    for (int r = 0; r < 2; r++) {
        float* l = r ? acc1 : acc0;
        float m = -1e30f;
        #pragma unroll
        for (int k = 0; k < 16; k++) m = fmaxf(m, l[k]);
        #pragma unroll
        for (int o = 16; o > 0; o >>= 1)
            m = fmaxf(m, __shfl_xor_sync(0xffffffffu, m, o));
        float s = 0.f;
        #pragma unroll
        for (int k = 0; k < 16; k++) { l[k] = __expf(l[k] - m); s += l[k]; }
        #pragma unroll
        for (int o = 16; o > 0; o >>= 1)
            s += __shfl_xor_sync(0xffffffffu, s, o);
        float inv = 1.f / s;
        #pragma unroll
        for (int k = 0; k < 16; k++) l[k] *= inv;
        float* gp = g_probs + (size_t)(rowb+r) * NH * LSEQ + n*LSEQ;
        #pragma unroll
        for (int k = 0; k < 16; k++) gp[lane + k*32] = l[k];
    }

    // --- out_s: shared v loads serve both rows ---
    float* feat0 = g_feat + (size_t)rowb     * NFEAT;
    float* feat1 = g_feat + (size_t)(rowb+1) * NFEAT;
    #pragma unroll
    for (int d = 0; d < DS; d++) {
        const float* vr = vsT + d*LSEQ + lane;
        float a0 = 0.f, a1 = 0.f;
        #pragma unroll
        for (int k = 0; k < 16; k++) {
            float v = vr[k*32];
            a0 += acc0[k]*v; a1 += acc1[k]*v;
        }
        #pragma unroll
        for (int o = 16; o > 0; o >>= 1) {
            a0 += __shfl_xor_sync(0xffffffffu, a0, o);
            a1 += __shfl_xor_sync(0xffffffffu, a1, o);
        }
        if (lane == 0) { feat0[n*DS + d] = a0; feat1[n*DS + d] = a1; }
    }
    #pragma unroll
    for (int pc = 0; pc < 12; pc++) {
        const float* vr = vpT + pc*LSEQ + lane;
        float a0 = 0.f, a1 = 0.f;
        #pragma unroll
        for (int k = 0; k < 16; k++) {
            float v = vr[k*32];
            a0 += acc0[k]*v; a1 += acc1[k]*v;
        }
        #pragma unroll
        for (int o = 16; o > 0; o >>= 1) {
            a0 += __shfl_xor_sync(0xffffffffu, a0, o);
            a1 += __shfl_xor_sync(0xffffffffu, a1, o);
        }
        if (lane == 0) { op_s[0][n*12 + pc] = a0; op_s[1][n*12 + pc] = a1; }
    }
    __syncthreads();

    if (tid < 64) {
        int r = tid >> 5, q = tid & 31;
        int nn = q >> 2, p = q & 3;
        int row = rowb + r;
        const float* rr = R + row*9;
        const float* tt = T + row*3;
        float* feat = r ? feat1 : feat0;
        float o0 = op_s[r][nn*12+p*3+0] - tt[0];
        float o1 = op_s[r][nn*12+p*3+1] - tt[1];
        float o2 = op_s[r][nn*12+p*3+2] - tt[2];
        float nsq = 0.f;
        #pragma unroll
        for (int c = 0; c < 3; c++) {
            float lc = o0*rr[c*3+0] + o1*rr[c*3+1] + o2*rr[c*3+2];
            feat[1152 + nn*12 + p*3 + c] = lc;
            nsq += lc*lc;
        }
        feat[1248 + nn*4 + p] = sqrtf(nsq);
    }
}

// ------ kernel 3c: out_pair = P @ E (streaming, probs in smem) -----------
#define K2_E0     0
#define K2_E1     8448
#define K2_P      16896
#define K2_FLOATS 20992

__global__ void __launch_bounds__(256) ipa_pair(const float* __restrict__ E)
{
    extern __shared__ float sm[];
    float* p_s = sm + K2_P;

    int row = blockIdx.x;
    int tid = threadIdx.x;
    int jl = tid >> 5, dl = tid & 31;

    unsigned sbase = (unsigned)__cvta_generic_to_shared(sm);
    const float* Ebi = E + (size_t)row * LSEQ * DPAIR;

    {
        const float4* esrc = (const float4*)Ebi;
        #pragma unroll
        for (int it = 0; it < 8; it++) {
            int g = it*256 + tid;
            int j = g >> 5, d = (g & 31) * 4;
            cp_async16(sbase + (unsigned)((K2_E0 + j*ROWF + d) * 4), esrc + g);
        }
        asm volatile("cp.async.commit_group;");
    }

    {
        const float4* gp4 = (const float4*)(g_probs + (size_t)row * NH * LSEQ);
        #pragma unroll
        for (int k = 0; k < 4; k++) {
            int o = tid + k*256;
            *(float4*)&p_s[o*4] = gp4[o];
        }
    }

    float acc[NH][4];
    #pragma unroll
    for (int n=0;n<NH;n++)
        #pragma unroll
        for (int c=0;c<4;c++) acc[n][c] = 0.f;

    for (int jt = 0; jt < LSEQ/TJ; jt++) {
        float* e_s = sm + ((jt & 1) ? K2_E1 : K2_E0);

        if (jt + 1 < LSEQ/TJ) {
            const float4* nsrc = (const float4*)(Ebi + (size_t)(jt+1)*TJ*DPAIR);
            unsigned bofs = (jt & 1) ? K2_E0 : K2_E1;
            #pragma unroll
            for (int it = 0; it < 8; it++) {
                int g = it*256 + tid;
                int j = g >> 5, d = (g & 31) * 4;
                cp_async16(sbase + (unsigned)((bofs + j*ROWF + d) * 4), nsrc + g);
            }
            asm volatile("cp.async.commit_group;");
            asm volatile("cp.async.wait_group 1;");
        } else {
            asm volatile("cp.async.wait_group 0;");
        }
        __syncthreads();

        int j0 = jt * TJ;
        #pragma unroll
        for (int jj = 0; jj < 8; jj++) {
            int j = jl*8 + jj;
            float4 ev = *(const float4*)(e_s + j*ROWF + dl*4);
            const float* pj = p_s + j0 + j;
            #pragma unroll
            for (int n=0;n<NH;n++) {
                float p = pj[n*LSEQ];
                acc[n][0] += p*ev.x; acc[n][1] += p*ev.y;
                acc[n][2] += p*ev.z; acc[n][3] += p*ev.w;
            }
        }
        __syncthreads();
    }

    float* red = sm + K2_E0;
    #pragma unroll
    for (int n=0;n<NH;n++)
        *(float4*)(red + (jl*NH + n)*128 + dl*4) =
            make_float4(acc[n][0], acc[n][1], acc[n][2], acc[n][3]);
    __syncthreads();

    float* feat = g_feat + (size_t)row * NFEAT + 128;
    #pragma unroll
    for (int k = 0; k < 4; k++) {
        int o = tid + k*256;
        int n = o >> 7, d = o & 127;
        float s = 0.f;
        #pragma unroll
        for (int w = 0; w < 8; w++) s += red[(w*NH+n)*128 + d];
        feat[n*128 + d] = s;
    }
}

// ------------- kernel 4: output GEMM, 4-way split-K partials --------------
__global__ void __launch_bounds__(64) out_gemm_sk(const float* __restrict__ Wout)
{
    __shared__ float As[2][16*36];
    __shared__ float Bs[2][16*32];
    const int tid = threadIdx.x;
    const int tx = tid & 7, ty = tid >> 3;
    const int row0 = blockIdx.y * 32;
    const int col0 = blockIdx.x * 32;
    const int kbase = blockIdx.z * KSPLIT;

    const int a_m0 = tid >> 2, a_k4 = tid & 3;
    const int b_k0 = tid >> 3, b_n4 = tid & 7;

    ull acc2[4][2];
    #pragma unroll
    for (int i=0;i<4;i++) { acc2[i][0]=0ull; acc2[i][1]=0ull; }

    {
        #pragma unroll
        for (int s=0;s<2;s++) {
            int m = a_m0 + s*16;
            float4 v = *(const float4*)&g_feat[(size_t)(row0+m)*NFEAT + kbase + a_k4*4];
            #pragma unroll
            for (int u=0;u<4;u++) As[0][(a_k4*4+u)*36 + m] = ((const float*)&v)[u];
            int k = b_k0 + s*8;
            *(float4*)&Bs[0][k*32 + b_n4*4] =
                *(const float4*)&Wout[(size_t)(kbase+k)*DRES + col0 + b_n4*4];
        }
    }
    __syncthreads();

    const int KB = KSPLIT/16;
    for (int kb = 0; kb < KB; kb++) {
        int cur = kb & 1;
        float4 va[2], vb[2];
        bool has = (kb+1 < KB);
        if (has) {
            int k0 = kbase + (kb+1)*16;
            #pragma unroll
            for (int s=0;s<2;s++) {
                int m = a_m0 + s*16;
                va[s] = *(const float4*)&g_feat[(size_t)(row0+m)*NFEAT + k0 + a_k4*4];
                int k = b_k0 + s*8;
                vb[s] = *(const float4*)&Wout[(size_t)(k0+k)*DRES + col0 + b_n4*4];
            }
        }
        #pragma unroll
        for (int kk = 0; kk < 16; kk++) {
            float4 a = *(const float4*)&As[cur][kk*36 + ty*4];
            float4 b = *(const float4*)&Bs[cur][kk*32 + tx*4];
            ull b01 = pk2(b.x, b.y), b23 = pk2(b.z, b.w);
            const float* ap = (const float*)&a;
            #pragma unroll
            for (int i=0;i<4;i++) {
                ull aa = pk2(ap[i], ap[i]);
                acc2[i][0] = ffma2(aa, b01, acc2[i][0]);
                acc2[i][1] = ffma2(aa, b23, acc2[i][1]);
            }
        }
        if (has) {
            int nxt = cur ^ 1;
            #pragma unroll
            for (int s=0;s<2;s++) {
                int m = a_m0 + s*16;
                #pragma unroll
                for (int u=0;u<4;u++) As[nxt][(a_k4*4+u)*36 + m] = ((const float*)&va[s])[u];
                int k = b_k0 + s*8;
                *(float4*)&Bs[nxt][k*32 + b_n4*4] = vb[s];
            }
        }
        __syncthreads();
    }

    float* dst = g_opart + (size_t)blockIdx.z * NROW * DRES;
    #pragma unroll
    for (int i=0;i<4;i++) {
        int row = row0 + ty*4 + i;
        float2 u0 = up2(acc2[i][0]), u1 = up2(acc2[i][1]);
        float4 o; o.x = u0.x; o.y = u0.y; o.z = u1.x; o.w = u1.y;
        *(float4*)&dst[(size_t)row*DRES + col0 + tx*4] = o;
    }
}

__global__ void __launch_bounds__(256) out_reduce(
    const float* __restrict__ bout, float* __restrict__ out)
{
    const int STRIDE4 = NROW*DRES/4;
    int i4 = blockIdx.x * 256 + threadIdx.x;
    const float4* p = (const float4*)g_opart;
    float4 a = p[i4], b = p[STRIDE4 + i4], c = p[2*STRIDE4 + i4], d = p[3*STRIDE4 + i4];
    int col = (i4 * 4) % DRES;
    float4 bb = *(const float4*)&bout[col];
    float4 o;
    o.x = a.x + b.x + c.x + d.x + bb.x;
    o.y = a.y + b.y + c.y + d.y + bb.y;
    o.z = a.z + b.z + c.z + d.z + bb.z;
    o.w = a.w + b.w + c.w + d.w + bb.w;
    ((float4*)out)[i4] = o;
}

// ---------------- launch ----------------
extern "C" void kernel_launch(void* const* d_in, const int* in_sizes, int n_in,
                              void* d_out, int out_size)
{
    const float* x     = (const float*)d_in[0];
    const float* e     = (const float*)d_in[1];
    const float* r     = (const float*)d_in[2];
    const float* t     = (const float*)d_in[3];
    const float* Wqs   = (const float*)d_in[4];
    const float* Wks   = (const float*)d_in[5];
    const float* Wvs   = (const float*)d_in[6];
    const float* Wpb   = (const float*)d_in[7];
    const float* Wqp   = (const float*)d_in[8];
    const float* Wkp   = (const float*)d_in[9];
    const float* Wvp   = (const float*)d_in[10];
    const float* gamma = (const float*)d_in[11];
    const float* Wout  = (const float*)d_in[12];
    const float* bout  = (const float*)d_in[13];
    float* out = (float*)d_out;

    proj_gemm<<<dim3(21, 32), 64>>>(x, Wqs, Wks, Wvs, Wqp, Wkp, Wvp);
    point_transform<<<NROW, 96>>>(r, t);

    cudaFuncSetAttribute(ipa_bias, cudaFuncAttributeMaxDynamicSharedMemorySize,
                         BK_FLOATS * (int)sizeof(float));
    ipa_bias<<<NROW, 256, BK_FLOATS * sizeof(float)>>>(e, Wpb);

    ipa_logits<<<NROW/2, 256>>>(r, t, gamma);

    cudaFuncSetAttribute(ipa_pair, cudaFuncAttributeMaxDynamicSharedMemorySize,
                         K2_FLOATS * (int)sizeof(float));
    ipa_pair<<<NROW, 256, K2_FLOATS * sizeof(float)>>>(e);

    out_gemm_sk<<<dim3(12, 32, NSPLIT), 64>>>(Wout);
    out_reduce<<<NROW*DRES/4/256, 256>>>(bout, out);
}

// round 17
// speedup vs baseline: 1.4233x; 1.0055x over previous
#include <cuda_runtime.h>
#include <math.h>

#define NH      8
#define LSEQ    512
#define DRES    384
#define DPAIR   128
#define DS      16
#define TJ      64
#define ROWF    132
#define NROW    1024
#define NFEAT   1280
#define NSPLIT  4
#define KSPLIT  (NFEAT/NSPLIT)
#define QB      4

#define SCALE_SCALAR 0.25f
#define SCALE_POINT  0.2357022603955158f   /* 18^-0.5 */
#define SCALE_TOTAL  0.5773502691896258f   /* 3^-0.5  */

typedef unsigned long long ull;

__device__ __forceinline__ ull pk2(float x, float y) {
    ull r; asm("mov.b64 %0,{%1,%2};" : "=l"(r) : "f"(x), "f"(y)); return r;
}
__device__ __forceinline__ ull ffma2(ull a, ull b, ull c) {
    ull d; asm("fma.rn.f32x2 %0,%1,%2,%3;" : "=l"(d) : "l"(a), "l"(b), "l"(c)); return d;
}
__device__ __forceinline__ float2 up2(ull v) {
    float2 r; asm("mov.b64 {%0,%1},%2;" : "=f"(r.x), "=f"(r.y) : "l"(v)); return r;
}
__device__ __forceinline__ void cp_async16(unsigned smem_addr, const void* gptr) {
    asm volatile("cp.async.cg.shared.global [%0], [%1], 16;"
                 :: "r"(smem_addr), "l"(gptr));
}

// ---------------- scratch (device globals; no allocation) ----------------
__device__ float g_qs[2*NH*LSEQ*DS];
__device__ float g_ksT[2*NH*DS*LSEQ];     // [b][n][d][l]
__device__ float g_vsT[2*NH*DS*LSEQ];     // [b][n][d][l]
__device__ float g_qp[2*NH*LSEQ*12];
__device__ float g_kpT[2*NH*12*LSEQ];     // [b][n][pc][l]
__device__ float g_vpT[2*NH*12*LSEQ];     // [b][n][pc][l]
__device__ float g_kk2[2*NH*LSEQ];        // sum over p,c of kp^2
__device__ float g_praw[NROW*288];
__device__ float g_feat[(size_t)NROW*NFEAT];
__device__ float g_opart[(size_t)NSPLIT*NROW*DRES];
__device__ float g_probs[(size_t)NROW*NH*LSEQ];
__device__ float g_bias[(size_t)NROW*NH*LSEQ];

// ---------------- kernel 1: projection GEMM ------------------------------
__global__ void __launch_bounds__(64) proj_gemm(
    const float* __restrict__ X,
    const float* __restrict__ Wqs, const float* __restrict__ Wks,
    const float* __restrict__ Wvs, const float* __restrict__ Wqp,
    const float* __restrict__ Wkp, const float* __restrict__ Wvp)
{
    __shared__ float As[2][16*36];
    __shared__ float Bs[2][16*32];
    const int tid = threadIdx.x;
    const int tx = tid & 7, ty = tid >> 3;
    const int row0 = blockIdx.y * 32;
    const int col0 = blockIdx.x * 32;

    const float* Wseg; int segw, cl0;
    if (col0 < 384) {
        int sg = col0 >> 7;
        Wseg = (sg==0) ? Wqs : ((sg==1) ? Wks : Wvs);
        segw = 128; cl0 = col0 & 127;
    } else {
        int c2 = col0 - 384; int sg = c2 / 96;
        Wseg = (sg==0) ? Wqp : ((sg==1) ? Wkp : Wvp);
        segw = 96; cl0 = c2 - sg*96;
    }

    const int a_m0 = tid >> 2, a_k4 = tid & 3;
    const int b_k0 = tid >> 3, b_n4 = tid & 7;

    float acc[4][4];
    #pragma unroll
    for (int i=0;i<4;i++)
        #pragma unroll
        for (int j=0;j<4;j++) acc[i][j]=0.f;

    {
        #pragma unroll
        for (int s=0;s<2;s++) {
            int m = a_m0 + s*16;
            float4 v = *(const float4*)&X[(size_t)(row0+m)*DRES + a_k4*4];
            #pragma unroll
            for (int u=0;u<4;u++) As[0][(a_k4*4+u)*36 + m] = ((const float*)&v)[u];
            int k = b_k0 + s*8;
            *(float4*)&Bs[0][k*32 + b_n4*4] =
                *(const float4*)&Wseg[(size_t)k*segw + cl0 + b_n4*4];
        }
    }
    __syncthreads();

    const int KB = DRES/16;
    for (int kb = 0; kb < KB; kb++) {
        int cur = kb & 1;
        float4 va[2], vb[2];
        bool has = (kb+1 < KB);
        if (has) {
            int k0 = (kb+1)*16;
            #pragma unroll
            for (int s=0;s<2;s++) {
                int m = a_m0 + s*16;
                va[s] = *(const float4*)&X[(size_t)(row0+m)*DRES + k0 + a_k4*4];
                int k = b_k0 + s*8;
                vb[s] = *(const float4*)&Wseg[(size_t)(k0+k)*segw + cl0 + b_n4*4];
            }
        }
        #pragma unroll
        for (int kk = 0; kk < 16; kk++) {
            float4 a = *(const float4*)&As[cur][kk*36 + ty*4];
            float4 b = *(const float4*)&Bs[cur][kk*32 + tx*4];
            const float* ap = (const float*)&a;
            const float* bp = (const float*)&b;
            #pragma unroll
            for (int i=0;i<4;i++)
                #pragma unroll
                for (int j=0;j<4;j++) acc[i][j] += ap[i]*bp[j];
        }
        if (has) {
            int nxt = cur ^ 1;
            #pragma unroll
            for (int s=0;s<2;s++) {
                int m = a_m0 + s*16;
                #pragma unroll
                for (int u=0;u<4;u++) As[nxt][(a_k4*4+u)*36 + m] = ((const float*)&va[s])[u];
                int k = b_k0 + s*8;
                *(float4*)&Bs[nxt][k*32 + b_n4*4] = vb[s];
            }
        }
        __syncthreads();
    }

    #pragma unroll
    for (int i=0;i<4;i++) {
        int row = row0 + ty*4 + i;
        int b = row >> 9, l = row & 511;
        #pragma unroll
        for (int j=0;j<4;j++) {
            int col = col0 + tx*4 + j;
            float v = acc[i][j];
            if (col < 384) {
                int sg = col >> 7;
                int n = (col & 127) >> 4, d = col & 15;
                if (sg == 0)
                    g_qs[(((b*NH)+n)*LSEQ + l)*DS + d] = v;
                else if (sg == 1)
                    g_ksT[(((b*NH)+n)*DS + d)*LSEQ + l] = v;
                else
                    g_vsT[(((b*NH)+n)*DS + d)*LSEQ + l] = v;
            } else {
                g_praw[row*288 + (col-384)] = v;
            }
        }
    }
}

// ------ kernel 2: euclid transform of projected points + kk2 -------------
__global__ void point_transform(const float* __restrict__ R, const float* __restrict__ T)
{
    __shared__ float kkp[32];
    int row = blockIdx.x;
    int b = row >> 9, l = row & 511;
    int t = threadIdx.x;
    if (t < 96) {
        int tensor = t / 32, idx = t % 32;
        int n = idx >> 2, p = idx & 3;
        const float* xr = &g_praw[row*288 + tensor*96 + n*12 + p*3];
        const float* rr = &R[row*9];
        const float* tt = &T[row*3];
        float x0 = xr[0], x1 = xr[1], x2 = xr[2];
        float o[3];
        #pragma unroll
        for (int c = 0; c < 3; c++)
            o[c] = x0*rr[0*3+c] + x1*rr[1*3+c] + x2*rr[2*3+c] + tt[c];
        if (tensor == 0) {
            float* dst = g_qp + (((b*NH)+n)*LSEQ + l)*12 + p*3;
            #pragma unroll
            for (int c = 0; c < 3; c++) dst[c] = o[c];
        } else {
            float* base = (tensor==1) ? g_kpT : g_vpT;
            #pragma unroll
            for (int c = 0; c < 3; c++)
                base[(((b*NH)+n)*12 + p*3 + c)*LSEQ + l] = o[c];
            if (tensor == 1)
                kkp[idx] = o[0]*o[0] + o[1]*o[1] + o[2]*o[2];
        }
    }
    __syncthreads();
    if (t < 8)
        g_kk2[(b*NH + t)*LSEQ + l] = kkp[t*4] + kkp[t*4+1] + kkp[t*4+2] + kkp[t*4+3];
}

// -------- kernel 3a: bias = e @ Wpb, streaming ----------------------------
#define BK_E0     0
#define BK_E1     8448
#define BK_WPB    16896
#define BK_PART   17920
#define BK_FLOATS 20224

__global__ void __launch_bounds__(256) ipa_bias(
    const float* __restrict__ E, const float* __restrict__ Wpb)
{
    extern __shared__ float sm[];
    float* Wpb_s  = sm + BK_WPB;
    float* part_s = sm + BK_PART;

    int row = blockIdx.x;
    int tid = threadIdx.x;

    unsigned sbase = (unsigned)__cvta_generic_to_shared(sm);
    const float* Ebi = E + (size_t)row * LSEQ * DPAIR;

    {
        const float4* esrc = (const float4*)Ebi;
        #pragma unroll
        for (int it = 0; it < 8; it++) {
            int g = it*256 + tid;
            int j = g >> 5, d = (g & 31) * 4;
            cp_async16(sbase + (unsigned)((BK_E0 + j*ROWF + d) * 4), esrc + g);
        }
        asm volatile("cp.async.commit_group;");
    }

    for (int k = tid; k < DPAIR*NH; k += 256) Wpb_s[k] = Wpb[k];

    float* gb = g_bias + (size_t)row * NH * LSEQ;

    for (int jt = 0; jt < LSEQ/TJ; jt++) {
        float* e_s = sm + ((jt & 1) ? BK_E1 : BK_E0);

        if (jt + 1 < LSEQ/TJ) {
            const float4* nsrc = (const float4*)(Ebi + (size_t)(jt+1)*TJ*DPAIR);
            unsigned bofs = (jt & 1) ? BK_E0 : BK_E1;
            #pragma unroll
            for (int it = 0; it < 8; it++) {
                int g = it*256 + tid;
                int j = g >> 5, d = (g & 31) * 4;
                cp_async16(sbase + (unsigned)((bofs + j*ROWF + d) * 4), nsrc + g);
            }
            asm volatile("cp.async.commit_group;");
            asm volatile("cp.async.wait_group 1;");
        } else {
            asm volatile("cp.async.wait_group 0;");
        }
        __syncthreads();

        int j0 = jt * TJ;

        {
            int j = tid & 63, quad = tid >> 6;
            float pb[NH];
            #pragma unroll
            for (int n=0;n<NH;n++) pb[n] = 0.f;
            const float4* er4 = (const float4*)(e_s + j*ROWF + quad*32);
            #pragma unroll
            for (int d4 = 0; d4 < 8; d4++) {
                float4 ev = er4[d4];
                const float* evp = (const float*)&ev;
                #pragma unroll
                for (int r = 0; r < 4; r++) {
                    const float* wrow = Wpb_s + (quad*32 + d4*4 + r)*NH;
                    float4 wA = *(const float4*)(wrow);
                    float4 wB = *(const float4*)(wrow + 4);
                    float e1 = evp[r];
                    pb[0] += e1*wA.x; pb[1] += e1*wA.y;
                    pb[2] += e1*wA.z; pb[3] += e1*wA.w;
                    pb[4] += e1*wB.x; pb[5] += e1*wB.y;
                    pb[6] += e1*wB.z; pb[7] += e1*wB.w;
                }
            }
            float* po = part_s + (quad*64 + j)*9;
            #pragma unroll
            for (int n=0;n<NH;n++) po[n] = pb[n];
        }
        __syncthreads();

        {
            int j = tid & 63, nb = tid >> 6;
            #pragma unroll
            for (int h = 0; h < 2; h++) {
                int n = nb + h*4;
                float bias = part_s[(0*64+j)*9+n] + part_s[(1*64+j)*9+n]
                           + part_s[(2*64+j)*9+n] + part_s[(3*64+j)*9+n];
                gb[n*LSEQ + j0 + j] = bias;
            }
        }
    }
}

// ---- kernel 3b: logits+softmax+out_s/out_p, 4 queries per block ---------
__global__ void __launch_bounds__(256) ipa_logits(
    const float* __restrict__ R, const float* __restrict__ T,
    const float* __restrict__ gamma)
{
    __shared__ float qs_s[QB][128];
    __shared__ float qp_s[QB][96];
    __shared__ float qq2_s[QB][8];
    __shared__ float op_s[QB][96];
    __shared__ float gam_s[8];

    int rowb = blockIdx.x * QB;
    int b = rowb >> 9;
    int tid = threadIdx.x;
    int warp = tid >> 5, lane = tid & 31;

    #pragma unroll
    for (int s = 0; s < 2; s++) {
        int o = tid + s*256;                 // 512 = QB*128
        int r = o >> 7, q = o & 127;
        int n = q >> 4, d = q & 15;
        qs_s[r][q] = g_qs[((b*NH+n)*LSEQ + ((rowb+r) & 511))*DS + d];
    }
    #pragma unroll
    for (int s = 0; s < 2; s++) {
        int o = tid + s*256;                 // need 384 = QB*96
        if (o < QB*96) {
            int r = o / 96, q = o - r*96;
            int n = q/12, pc = q - n*12;
            qp_s[r][q] = g_qp[((b*NH+n)*LSEQ + ((rowb+r) & 511))*12 + pc];
        }
    }
    if (tid < 8) gam_s[tid] = gamma[tid];
    __syncthreads();
    if (tid < QB*8) {
        int r = tid >> 3, n = tid & 7;
        float s = 0.f;
        #pragma unroll
        for (int pc = 0; pc < 12; pc++) { float v = qp_s[r][n*12+pc]; s += v*v; }
        qq2_s[r][n] = s;
    }
    __syncthreads();

    int n = warp;
    float spg = SCALE_POINT * gam_s[n];
    const float* ksT = g_ksT + (size_t)(b*NH+n)*DS*LSEQ;
    const float* kpT = g_kpT + (size_t)(b*NH+n)*12*LSEQ;
    const float* vsT = g_vsT + (size_t)(b*NH+n)*DS*LSEQ;
    const float* vpT = g_vpT + (size_t)(b*NH+n)*12*LSEQ;

    // --- combined-scale accumulation for 4 queries ---
    float acc[QB][16];
    #pragma unroll
    for (int r = 0; r < QB; r++)
        #pragma unroll
        for (int k = 0; k < 16; k++) acc[r][k] = 0.f;

    #pragma unroll
    for (int d = 0; d < DS; d++) {
        float q0 = SCALE_SCALAR * qs_s[0][n*DS + d];
        float q1 = SCALE_SCALAR * qs_s[1][n*DS + d];
        float q2 = SCALE_SCALAR * qs_s[2][n*DS + d];
        float q3 = SCALE_SCALAR * qs_s[3][n*DS + d];
        const float* kr = ksT + d*LSEQ + lane;
        #pragma unroll
        for (int k = 0; k < 16; k++) {
            float kv = kr[k*32];
            acc[0][k] += q0*kv; acc[1][k] += q1*kv;
            acc[2][k] += q2*kv; acc[3][k] += q3*kv;
        }
    }
    #pragma unroll
    for (int pc = 0; pc < 12; pc++) {
        float q0 = spg * qp_s[0][n*12 + pc];
        float q1 = spg * qp_s[1][n*12 + pc];
        float q2 = spg * qp_s[2][n*12 + pc];
        float q3 = spg * qp_s[3][n*12 + pc];
        const float* kp = kpT + pc*LSEQ + lane;
        #pragma unroll
        for (int k = 0; k < 16; k++) {
            float kv = kp[k*32];
            acc[0][k] += q0*kv; acc[1][k] += q1*kv;
            acc[2][k] += q2*kv; acc[3][k] += q3*kv;
        }
    }
    // --- finish logits: + bias - 0.5*SPg*(qq2 + kk2) ---
    {
        float c[QB];
        #pragma unroll
        for (int r = 0; r < QB; r++) c[r] = -0.5f*spg*qq2_s[r][n];
        const float* kk = g_kk2 + (size_t)(b*NH+n)*LSEQ + lane;
        #pragma unroll
        for (int k = 0; k < 16; k++) {
            float kkt = -0.5f*spg*kk[k*32];
            #pragma unroll
            for (int r = 0; r < QB; r++) {
                const float* gb = g_bias + (size_t)(rowb+r) * NH * LSEQ + n*LSEQ;
                acc[r][k] = SCALE_TOTAL*(acc[r][k] + gb[lane + k*32] + c[r] + kkt);
            }
        }
    }

    // --- softmax per row (warp = head) ---
    #pragma unroll
    for (int r = 0; r < QB; r++) {
        float* l = acc[r];
        float m = -1e30f;
        #pragma unroll
        for (int k = 0; k < 16; k++) m = fmaxf(m, l[k]);
        #pragma unroll
        for (int o = 16; o > 0; o >>= 1)
            m = fmaxf(m, __shfl_xor_sync(0xffffffffu, m, o));
        float s = 0.f;
        #pragma unroll
        for (int k = 0; k < 16; k++) { l[k] = __expf(l[k] - m); s += l[k]; }
        #pragma unroll
        for (int o = 16; o > 0; o >>= 1)
            s += __shfl_xor_sync(0xffffffffu, s, o);
        float inv = 1.f / s;
        #pragma unroll
        for (int k = 0; k < 16; k++) l[k] *= inv;
        float* gp = g_probs + (size_t)(rowb+r) * NH * LSEQ + n*LSEQ;
        #pragma unroll
        for (int k = 0; k < 16; k++) gp[lane + k*32] = l[k];
    }

    // --- out_s: shared v loads serve all 4 rows ---
    #pragma unroll
    for (int d = 0; d < DS; d++) {
        const float* vr = vsT + d*LSEQ + lane;
        float a[QB] = {0.f, 0.f, 0.f, 0.f};
        #pragma unroll
        for (int k = 0; k < 16; k++) {
            float v = vr[k*32];
            #pragma unroll
            for (int r = 0; r < QB; r++) a[r] += acc[r][k]*v;
        }
        #pragma unroll
        for (int o = 16; o > 0; o >>= 1)
            #pragma unroll
            for (int r = 0; r < QB; r++)
                a[r] += __shfl_xor_sync(0xffffffffu, a[r], o);
        if (lane == 0) {
            #pragma unroll
            for (int r = 0; r < QB; r++)
                g_feat[(size_t)(rowb+r)*NFEAT + n*DS + d] = a[r];
        }
    }
    #pragma unroll
    for (int pc = 0; pc < 12; pc++) {
        const float* vr = vpT + pc*LSEQ + lane;
        float a[QB] = {0.f, 0.f, 0.f, 0.f};
        #pragma unroll
        for (int k = 0; k < 16; k++) {
            float v = vr[k*32];
            #pragma unroll
            for (int r = 0; r < QB; r++) a[r] += acc[r][k]*v;
        }
        #pragma unroll
        for (int o = 16; o > 0; o >>= 1)
            #pragma unroll
            for (int r = 0; r < QB; r++)
                a[r] += __shfl_xor_sync(0xffffffffu, a[r], o);
        if (lane == 0) {
            #pragma unroll
            for (int r = 0; r < QB; r++) op_s[r][n*12 + pc] = a[r];
        }
    }
    __syncthreads();

    if (tid < QB*32) {
        int r = tid >> 5, q = tid & 31;
        int nn = q >> 2, p = q & 3;
        int row = rowb + r;
        const float* rr = R + row*9;
        const float* tt = T + row*3;
        float* feat = g_feat + (size_t)row * NFEAT;
        float o0 = op_s[r][nn*12+p*3+0] - tt[0];
        float o1 = op_s[r][nn*12+p*3+1] - tt[1];
        float o2 = op_s[r][nn*12+p*3+2] - tt[2];
        float nsq = 0.f;
        #pragma unroll
        for (int c = 0; c < 3; c++) {
            float lc = o0*rr[c*3+0] + o1*rr[c*3+1] + o2*rr[c*3+2];
            feat[1152 + nn*12 + p*3 + c] = lc;
            nsq += lc*lc;
        }
        feat[1248 + nn*4 + p] = sqrtf(nsq);
    }
}

// ------ kernel 3c: out_pair = P @ E (streaming, probs in smem) -----------
#define K2_E0     0
#define K2_E1     8448
#define K2_P      16896
#define K2_FLOATS 20992

__global__ void __launch_bounds__(256) ipa_pair(const float* __restrict__ E)
{
    extern __shared__ float sm[];
    float* p_s = sm + K2_P;

    int row = blockIdx.x;
    int tid = threadIdx.x;
    int jl = tid >> 5, dl = tid & 31;

    unsigned sbase = (unsigned)__cvta_generic_to_shared(sm);
    const float* Ebi = E + (size_t)row * LSEQ * DPAIR;

    {
        const float4* esrc = (const float4*)Ebi;
        #pragma unroll
        for (int it = 0; it < 8; it++) {
            int g = it*256 + tid;
            int j = g >> 5, d = (g & 31) * 4;
            cp_async16(sbase + (unsigned)((K2_E0 + j*ROWF + d) * 4), esrc + g);
        }
        asm volatile("cp.async.commit_group;");
    }

    {
        const float4* gp4 = (const float4*)(g_probs + (size_t)row * NH * LSEQ);
        #pragma unroll
        for (int k = 0; k < 4; k++) {
            int o = tid + k*256;
            *(float4*)&p_s[o*4] = gp4[o];
        }
    }

    float acc[NH][4];
    #pragma unroll
    for (int n=0;n<NH;n++)
        #pragma unroll
        for (int c=0;c<4;c++) acc[n][c] = 0.f;

    for (int jt = 0; jt < LSEQ/TJ; jt++) {
        float* e_s = sm + ((jt & 1) ? K2_E1 : K2_E0);

        if (jt + 1 < LSEQ/TJ) {
            const float4* nsrc = (const float4*)(Ebi + (size_t)(jt+1)*TJ*DPAIR);
            unsigned bofs = (jt & 1) ? K2_E0 : K2_E1;
            #pragma unroll
            for (int it = 0; it < 8; it++) {
                int g = it*256 + tid;
                int j = g >> 5, d = (g & 31) * 4;
                cp_async16(sbase + (unsigned)((bofs + j*ROWF + d) * 4), nsrc + g);
            }
            asm volatile("cp.async.commit_group;");
            asm volatile("cp.async.wait_group 1;");
        } else {
            asm volatile("cp.async.wait_group 0;");
        }
        __syncthreads();

        int j0 = jt * TJ;
        #pragma unroll
        for (int jj = 0; jj < 8; jj++) {
            int j = jl*8 + jj;
            float4 ev = *(const float4*)(e_s + j*ROWF + dl*4);
            const float* pj = p_s + j0 + j;
            #pragma unroll
            for (int n=0;n<NH;n++) {
                float p = pj[n*LSEQ];
                acc[n][0] += p*ev.x; acc[n][1] += p*ev.y;
                acc[n][2] += p*ev.z; acc[n][3] += p*ev.w;
            }
        }
        __syncthreads();
    }

    float* red = sm + K2_E0;
    #pragma unroll
    for (int n=0;n<NH;n++)
        *(float4*)(red + (jl*NH + n)*128 + dl*4) =
            make_float4(acc[n][0], acc[n][1], acc[n][2], acc[n][3]);
    __syncthreads();

    float* feat = g_feat + (size_t)row * NFEAT + 128;
    #pragma unroll
    for (int k = 0; k < 4; k++) {
        int o = tid + k*256;
        int n = o >> 7, d = o & 127;
        float s = 0.f;
        #pragma unroll
        for (int w = 0; w < 8; w++) s += red[(w*NH+n)*128 + d];
        feat[n*128 + d] = s;
    }
}

// ------------- kernel 4: output GEMM, 4-way split-K partials --------------
__global__ void __launch_bounds__(64) out_gemm_sk(const float* __restrict__ Wout)
{
    __shared__ float As[2][16*36];
    __shared__ float Bs[2][16*32];
    const int tid = threadIdx.x;
    const int tx = tid & 7, ty = tid >> 3;
    const int row0 = blockIdx.y * 32;
    const int col0 = blockIdx.x * 32;
    const int kbase = blockIdx.z * KSPLIT;

    const int a_m0 = tid >> 2, a_k4 = tid & 3;
    const int b_k0 = tid >> 3, b_n4 = tid & 7;

    ull acc2[4][2];
    #pragma unroll
    for (int i=0;i<4;i++) { acc2[i][0]=0ull; acc2[i][1]=0ull; }

    {
        #pragma unroll
        for (int s=0;s<2;s++) {
            int m = a_m0 + s*16;
            float4 v = *(const float4*)&g_feat[(size_t)(row0+m)*NFEAT + kbase + a_k4*4];
            #pragma unroll
            for (int u=0;u<4;u++) As[0][(a_k4*4+u)*36 + m] = ((const float*)&v)[u];
            int k = b_k0 + s*8;
            *(float4*)&Bs[0][k*32 + b_n4*4] =
                *(const float4*)&Wout[(size_t)(kbase+k)*DRES + col0 + b_n4*4];
        }
    }
    __syncthreads();

    const int KB = KSPLIT/16;
    for (int kb = 0; kb < KB; kb++) {
        int cur = kb & 1;
        float4 va[2], vb[2];
        bool has = (kb+1 < KB);
        if (has) {
            int k0 = kbase + (kb+1)*16;
            #pragma unroll
            for (int s=0;s<2;s++) {
                int m = a_m0 + s*16;
                va[s] = *(const float4*)&g_feat[(size_t)(row0+m)*NFEAT + k0 + a_k4*4];
                int k = b_k0 + s*8;
                vb[s] = *(const float4*)&Wout[(size_t)(k0+k)*DRES + col0 + b_n4*4];
            }
        }
        #pragma unroll
        for (int kk = 0; kk < 16; kk++) {
            float4 a = *(const float4*)&As[cur][kk*36 + ty*4];
            float4 b = *(const float4*)&Bs[cur][kk*32 + tx*4];
            ull b01 = pk2(b.x, b.y), b23 = pk2(b.z, b.w);
            const float* ap = (const float*)&a;
            #pragma unroll
            for (int i=0;i<4;i++) {
                ull aa = pk2(ap[i], ap[i]);
                acc2[i][0] = ffma2(aa, b01, acc2[i][0]);
                acc2[i][1] = ffma2(aa, b23, acc2[i][1]);
            }
        }
        if (has) {
            int nxt = cur ^ 1;
            #pragma unroll
            for (int s=0;s<2;s++) {
                int m = a_m0 + s*16;
                #pragma unroll
                for (int u=0;u<4;u++) As[nxt][(a_k4*4+u)*36 + m] = ((const float*)&va[s])[u];
                int k = b_k0 + s*8;
                *(float4*)&Bs[nxt][k*32 + b_n4*4] = vb[s];
            }
        }
        __syncthreads();
    }

    float* dst = g_opart + (size_t)blockIdx.z * NROW * DRES;
    #pragma unroll
    for (int i=0;i<4;i++) {
        int row = row0 + ty*4 + i;
        float2 u0 = up2(acc2[i][0]), u1 = up2(acc2[i][1]);
        float4 o; o.x = u0.x; o.y = u0.y; o.z = u1.x; o.w = u1.y;
        *(float4*)&dst[(size_t)row*DRES + col0 + tx*4] = o;
    }
}

__global__ void __launch_bounds__(256) out_reduce(
    const float* __restrict__ bout, float* __restrict__ out)
{
    const int STRIDE4 = NROW*DRES/4;
    int i4 = blockIdx.x * 256 + threadIdx.x;
    const float4* p = (const float4*)g_opart;
    float4 a = p[i4], b = p[STRIDE4 + i4], c = p[2*STRIDE4 + i4], d = p[3*STRIDE4 + i4];
    int col = (i4 * 4) % DRES;
    float4 bb = *(const float4*)&bout[col];
    float4 o;
    o.x = a.x + b.x + c.x + d.x + bb.x;
    o.y = a.y + b.y + c.y + d.y + bb.y;
    o.z = a.z + b.z + c.z + d.z + bb.z;
    o.w = a.w + b.w + c.w + d.w + bb.w;
    ((float4*)out)[i4] = o;
}

// ---------------- launch ----------------
extern "C" void kernel_launch(void* const* d_in, const int* in_sizes, int n_in,
                              void* d_out, int out_size)
{
    const float* x     = (const float*)d_in[0];
    const float* e     = (const float*)d_in[1];
    const float* r     = (const float*)d_in[2];
    const float* t     = (const float*)d_in[3];
    const float* Wqs   = (const float*)d_in[4];
    const float* Wks   = (const float*)d_in[5];
    const float* Wvs   = (const float*)d_in[6];
    const float* Wpb   = (const float*)d_in[7];
    const float* Wqp   = (const float*)d_in[8];
    const float* Wkp   = (const float*)d_in[9];
    const float* Wvp   = (const float*)d_in[10];
    const float* gamma = (const float*)d_in[11];
    const float* Wout  = (const float*)d_in[12];
    const float* bout  = (const float*)d_in[13];
    float* out = (float*)d_out;

    proj_gemm<<<dim3(21, 32), 64>>>(x, Wqs, Wks, Wvs, Wqp, Wkp, Wvp);
    point_transform<<<NROW, 96>>>(r, t);

    cudaFuncSetAttribute(ipa_bias, cudaFuncAttributeMaxDynamicSharedMemorySize,
                         BK_FLOATS * (int)sizeof(float));
    ipa_bias<<<NROW, 256, BK_FLOATS * sizeof(float)>>>(e, Wpb);

    ipa_logits<<<NROW/QB, 256>>>(r, t, gamma);

    cudaFuncSetAttribute(ipa_pair, cudaFuncAttributeMaxDynamicSharedMemorySize,
                         K2_FLOATS * (int)sizeof(float));
    ipa_pair<<<NROW, 256, K2_FLOATS * sizeof(float)>>>(e);

    out_gemm_sk<<<dim3(12, 32, NSPLIT), 64>>>(Wout);
    out_reduce<<<NROW*DRES/4/256, 256>>>(bout, out);
}